// round 6
// baseline (speedup 1.0000x reference)
#include <cuda_runtime.h>
#include <math.h>

#define NTOK 196
#define EMBD 256
#define HIDD 1024
#define NH   8
#define DHD  32
#define NB   148
#define NTHR 256

// ---------------- scratch (allocation-free: __device__ globals) ----------------
__device__ float g_part[16][NTOK * HIDD]; // split-K partials, reused per stage
__device__ float g_nrm1[2][NTOK * EMBD];  // LN1 outputs (residual base)
__device__ float g_q[2][NH][NTOK * DHD];  // deinterleaved Q  [n][d]
__device__ float g_k[2][NH][DHD * 200];   // deinterleaved K  [d][n] (pad 200)
__device__ float g_v[2][NH][NTOK * DHD];  // deinterleaved V  [n][d]
__device__ float g_attn[2][NTOK * EMBD];  // attention output
__device__ float g_l[2][NTOK * EMBD];     // LN2 outputs
__device__ float g_hid[2][NTOK * HIDD];   // FF hidden (post-GELU)
__device__ unsigned g_count = 0;
__device__ unsigned g_gen = 0;

// ---------------- grid-wide barrier (all NB blocks co-resident) ----------------
__device__ __forceinline__ void gsync()
{
    __syncthreads();
    if (threadIdx.x == 0) {
        __threadfence();
        unsigned gen = *(volatile unsigned*)&g_gen;
        if (atomicAdd(&g_count, 1u) == NB - 1u) {
            g_count = 0u;
            __threadfence();
            atomicAdd(&g_gen, 1u);
        } else {
            while (*(volatile unsigned*)&g_gen == gen) __nanosleep(32);
        }
        __threadfence();
    }
    __syncthreads();
}

// ---------------- packed fp32x2 FMA helpers ----------------
__device__ __forceinline__ void ffma2(unsigned long long& acc,
                                      unsigned long long a, unsigned long long b)
{
    asm("fma.rn.f32x2 %0, %1, %2, %0;" : "+l"(acc) : "l"(a), "l"(b));
}
__device__ __forceinline__ unsigned long long pk2(float x, float y)
{
    unsigned long long r;
    asm("mov.b64 %0, {%1, %2};" : "=l"(r) : "f"(x), "f"(y));
    return r;
}
__device__ __forceinline__ float2 up2(unsigned long long v)
{
    float2 r;
    asm("mov.b64 {%0, %1}, %2;" : "=f"(r.x), "=f"(r.y) : "l"(v));
    return r;
}

// ---------------- 32x128 GEMM tile, 2x8 microtile, f32x2 accum ----------------
// Cp[row0.., col0..] = A[M x K slice] @ B[K x N]; partial (no bias/act).
__device__ void gemm_tile(const float* __restrict__ A, int lda, int M,
                          const float* __restrict__ B, int ldb,
                          float* __restrict__ Cp, int ldc,
                          int row0, int col0, int kstart, int klen, float* sm)
{
    float (*As)[36] = (float(*)[36])sm;              // [16][36] padded
    float* Bs = sm + 16 * 36;                        // [16][128] flat

    int tid = threadIdx.x;
    int tx = tid & 15, ty = tid >> 4;                // ty 0..15 -> 2 rows each

    unsigned long long acc[2][4];
    #pragma unroll
    for (int i = 0; i < 2; i++)
        #pragma unroll
        for (int j = 0; j < 4; j++) acc[i][j] = 0ull;

    int ar = (tid >> 2) & 31, ak = (tid & 3) * 4;    // A loader (tid<128)
    bool aload = tid < 128;
    bool avalid = aload && (row0 + ar) < M;
    const float* Arow = A + (row0 + ar) * lda + kstart + ak;
    int brow = tid >> 5, bcol = (tid * 4) & 127;     // B loader

    for (int k0 = 0; k0 < klen; k0 += 16) {
        if (aload) {
            float4 av = make_float4(0.f, 0.f, 0.f, 0.f);
            if (avalid) av = *(const float4*)(Arow + k0);
            As[ak + 0][ar] = av.x; As[ak + 1][ar] = av.y;
            As[ak + 2][ar] = av.z; As[ak + 3][ar] = av.w;
        }
        const float* Bb = B + (kstart + k0) * ldb + col0;
        *(float4*)&Bs[brow * 128 + bcol] =
            *(const float4*)&Bb[brow * ldb + bcol];
        *(float4*)&Bs[(brow + 8) * 128 + bcol] =
            *(const float4*)&Bb[(brow + 8) * ldb + bcol];
        __syncthreads();

        #pragma unroll
        for (int k = 0; k < 16; k++) {
            float2 a = *(float2*)&As[k][ty * 2];
            ulonglong2 b01 = *(ulonglong2*)&Bs[k * 128 + tx * 8];
            ulonglong2 b23 = *(ulonglong2*)&Bs[k * 128 + tx * 8 + 4];
            unsigned long long a0 = pk2(a.x, a.x), a1 = pk2(a.y, a.y);
            ffma2(acc[0][0], a0, b01.x); ffma2(acc[0][1], a0, b01.y);
            ffma2(acc[0][2], a0, b23.x); ffma2(acc[0][3], a0, b23.y);
            ffma2(acc[1][0], a1, b01.x); ffma2(acc[1][1], a1, b01.y);
            ffma2(acc[1][2], a1, b23.x); ffma2(acc[1][3], a1, b23.y);
        }
        __syncthreads();
    }

    #pragma unroll
    for (int i = 0; i < 2; i++) {
        int r = row0 + ty * 2 + i;
        if (r < M) {
            float2 v0 = up2(acc[i][0]), v1 = up2(acc[i][1]);
            float2 v2 = up2(acc[i][2]), v3 = up2(acc[i][3]);
            float4 w0 = make_float4(v0.x, v0.y, v1.x, v1.y);
            float4 w1 = make_float4(v2.x, v2.y, v3.x, v3.y);
            *(float4*)&Cp[r * ldc + col0 + tx * 8]     = w0;
            *(float4*)&Cp[r * ldc + col0 + tx * 8 + 4] = w1;
        }
    }
}

// ---------------- block LayerNorm over 256-elem row (256 threads) -------------
__device__ __forceinline__ float ln_norm(float v, float w, float b, float* red)
{
    int tid = threadIdx.x;
    float t = v;
    #pragma unroll
    for (int off = 16; off; off >>= 1) t += __shfl_xor_sync(0xffffffffu, t, off);
    __syncthreads();
    if ((tid & 31) == 0) red[tid >> 5] = t;
    __syncthreads();
    float mean = (red[0] + red[1] + red[2] + red[3] +
                  red[4] + red[5] + red[6] + red[7]) * (1.0f / EMBD);
    float d = v - mean;
    t = d * d;
    #pragma unroll
    for (int off = 16; off; off >>= 1) t += __shfl_xor_sync(0xffffffffu, t, off);
    __syncthreads();
    if ((tid & 31) == 0) red[tid >> 5] = t;
    __syncthreads();
    float var = (red[0] + red[1] + red[2] + red[3] +
                 red[4] + red[5] + red[6] + red[7]) * (1.0f / EMBD);
    return d * rsqrtf(var + 1e-5f) * w + b;
}

// ---------------- attention smem layout (floats) ----------------
#define A_KS 0
#define A_VS (32 * 200)
#define A_SS (A_VS + NTOK * DHD)
#define A_QS (A_SS + 32 * 200)
#define A_IV (A_QS + 32 * 32)
#define SMEM_FLOATS (A_IV + 32)
#define SMEM_BYTES  (SMEM_FLOATS * 4)

__device__ void attn_tile(int qt, int h, int s, float* buf)
{
    float (*Ks)[200] = (float(*)[200])(buf + A_KS);
    float (*Vs)[DHD] = (float(*)[DHD])(buf + A_VS);
    float (*Ss)[200] = (float(*)[200])(buf + A_SS);
    float (*Qs)[DHD] = (float(*)[DHD])(buf + A_QS);
    float* inv = buf + A_IV;
    int tid = threadIdx.x;

    const float* gk = g_k[1 - s][h];
    const float* gv = g_v[1 - s][h];
    const float* gq = g_q[s][h];

    for (int i = tid; i < 32 * 50; i += NTHR)
        ((float4*)(buf + A_KS))[i] = ((const float4*)gk)[i];
    for (int i = tid; i < NTOK * 8; i += NTHR)
        ((float4*)(buf + A_VS))[i] = ((const float4*)gv)[i];
    for (int i = tid; i < 32 * 8; i += NTHR) {
        int q = i >> 3, d4 = (i & 7) << 2;
        int qg = qt * 32 + q;
        float4 v = make_float4(0.f, 0.f, 0.f, 0.f);
        if (qg < NTOK) v = *(const float4*)&gq[qg * DHD + d4];
        *(float4*)&Qs[q][d4] = v;
    }
    __syncthreads();

    // scores
    {
        int q = tid >> 3, g = tid & 7;
        float qr[32];
        #pragma unroll
        for (int d = 0; d < 32; d++) qr[d] = Qs[q][d];
        #pragma unroll
        for (int kk = 0; kk < 7; kk++) {
            int j0 = g * 4 + kk * 32;
            if (j0 >= NTOK) break;
            float a0 = 0.f, a1 = 0.f, a2 = 0.f, a3 = 0.f;
            #pragma unroll
            for (int d = 0; d < 32; d++) {
                float4 kv = *(float4*)&Ks[d][j0];
                a0 += qr[d] * kv.x; a1 += qr[d] * kv.y;
                a2 += qr[d] * kv.z; a3 += qr[d] * kv.w;
            }
            Ss[q][j0 + 0] = a0 * 0.0625f;
            Ss[q][j0 + 1] = a1 * 0.0625f;
            Ss[q][j0 + 2] = a2 * 0.0625f;
            Ss[q][j0 + 3] = a3 * 0.0625f;
        }
    }
    __syncthreads();

    // softmax
    {
        int w = tid >> 5, lane = tid & 31;
        for (int r = 0; r < 4; r++) {
            int q = w * 4 + r;
            float m = -1e30f;
            for (int j = lane; j < NTOK; j += 32) m = fmaxf(m, Ss[q][j]);
            #pragma unroll
            for (int off = 16; off; off >>= 1)
                m = fmaxf(m, __shfl_xor_sync(0xffffffffu, m, off));
            float sum = 0.f;
            for (int j = lane; j < NTOK; j += 32) {
                float e = __expf(Ss[q][j] - m);
                Ss[q][j] = e;
                sum += e;
            }
            #pragma unroll
            for (int off = 16; off; off >>= 1)
                sum += __shfl_xor_sync(0xffffffffu, sum, off);
            if (lane == 0) inv[q] = 1.0f / sum;
        }
    }
    __syncthreads();

    // PV
    {
        int q = tid >> 3, d0 = (tid & 7) * 4;
        float4 acc = make_float4(0.f, 0.f, 0.f, 0.f);
        for (int j = 0; j < NTOK; j += 2) {
            float p0 = Ss[q][j], p1 = Ss[q][j + 1];
            float4 v0 = *(float4*)&Vs[j][d0];
            float4 v1 = *(float4*)&Vs[j + 1][d0];
            acc.x += p0 * v0.x + p1 * v1.x;
            acc.y += p0 * v0.y + p1 * v1.y;
            acc.z += p0 * v0.z + p1 * v1.z;
            acc.w += p0 * v0.w + p1 * v1.w;
        }
        float iv = inv[q];
        acc.x *= iv; acc.y *= iv; acc.z *= iv; acc.w *= iv;
        int qg = qt * 32 + q;
        if (qg < NTOK)
            *(float4*)&g_attn[s][qg * EMBD + h * DHD + d0] = acc;
    }
}

// ---------------- fused persistent kernel ----------------
struct Params {
    const float *vis, *ir;
    const float *ln1w[2], *ln1b[2], *ln2w[2], *ln2b[2];
    const float *Wqkv[2], *bqkv[2], *Wp[2], *bp[2];
    const float *W1[2], *b1[2], *W2[2], *b2[2];
    float* out;
};

__global__ void __launch_bounds__(NTHR, 1) fused(Params p)
{
    extern __shared__ float sm[];
    int b = blockIdx.x;
    int tid = threadIdx.x;

    // ---- S0: QKV split-K=2 partial GEMMs (168 items) ----
    for (int it = b; it < 168; it += NB) {
        int t = it;
        int nt = t % 6; t /= 6;
        int mt = t % 7; t /= 7;
        int s = t & 1, ks = t >> 1;
        gemm_tile(s ? p.ir : p.vis, EMBD, NTOK, p.Wqkv[s], 768,
                  g_part[ks * 2 + s], 768, mt * 32, nt * 128, ks * 128, 128, sm);
    }
    // LN1 (all blocks; uniform trip count within block)
    for (int r = b; r < 2 * NTOK; r += NB) {
        int s = r >= NTOK;
        int n = s ? r - NTOK : r;
        float v = (s ? p.ir : p.vis)[n * EMBD + tid];
        g_nrm1[s][n * EMBD + tid] =
            ln_norm(v, p.ln1w[s][tid], p.ln1b[s][tid], sm);
    }
    gsync();

    // ---- S0.5: QKV reduce + bias + deinterleave ----
    {
        int tot = 2 * NTOK * 768;
        for (int e = b * NTHR + tid; e < tot; e += NB * NTHR) {
            int s = e / (NTOK * 768);
            int rem = e - s * (NTOK * 768);
            int n = rem / 768, c = rem - n * 768;
            float v = g_part[s][rem] + g_part[2 + s][rem] + p.bqkv[s][c];
            int hd = c / 3, t3 = c - hd * 3;
            int h = hd >> 5, d = hd & 31;
            if (t3 == 0)      g_q[s][h][n * DHD + d] = v;
            else if (t3 == 1) g_k[s][h][d * 200 + n] = v;
            else              g_v[s][h][n * DHD + d] = v;
        }
    }
    gsync();

    // ---- S1: cross attention (112 items) ----
    if (b < 112) {
        int t = b;
        int qt = t % 7; t /= 7;
        int h = t % 8;
        int s = t / 8;
        attn_tile(qt, h, s, sm);
    }
    gsync();

    // ---- S2: proj split-K=8 partial GEMMs (224 items, K=32 each) ----
    for (int it = b; it < 224; it += NB) {
        int t = it;
        int nt = t & 1; t >>= 1;
        int mt = t % 7; t /= 7;
        int s = t & 1, ks = t >> 1;      // ks 0..7
        gemm_tile(g_attn[s], EMBD, NTOK, p.Wp[s], EMBD,
                  g_part[ks * 2 + s], EMBD, mt * 32, nt * 128, ks * 32, 32, sm);
    }
    gsync();

    // ---- S3: proj reduce + bias + residual + LN2 ----
    for (int r = b; r < 2 * NTOK; r += NB) {
        int s = r >= NTOK;
        int n = s ? r - NTOK : r;
        int idx = n * EMBD + tid;
        float v = 0.f;
        #pragma unroll
        for (int ks = 0; ks < 8; ks++) v += g_part[ks * 2 + s][idx];
        v += p.bp[s][tid] + g_nrm1[s][idx];
        g_l[s][idx] = ln_norm(v, p.ln2w[s][tid], p.ln2b[s][tid], sm);
    }
    gsync();

    // ---- S4: FF1 split-K=2 partial GEMMs (224 items) ----
    for (int it = b; it < 224; it += NB) {
        int t = it;
        int nt = t & 7; t >>= 3;
        int mt = t % 7; t /= 7;
        int s = t & 1, ks = t >> 1;
        gemm_tile(g_l[s], EMBD, NTOK, p.W1[s], HIDD,
                  g_part[ks * 2 + s], HIDD, mt * 32, nt * 128, ks * 128, 128, sm);
    }
    gsync();

    // ---- S4.5: FF1 reduce + bias + exact GELU ----
    {
        int tot = 2 * NTOK * HIDD;
        for (int e = b * NTHR + tid; e < tot; e += NB * NTHR) {
            int s = e / (NTOK * HIDD);
            int rem = e - s * (NTOK * HIDD);
            int c = rem & 1023;
            float v = g_part[s][rem] + g_part[2 + s][rem] + p.b1[s][c];
            v = 0.5f * v * (1.0f + erff(v * 0.70710678118654752f));
            g_hid[s][rem] = v;
        }
    }
    gsync();

    // ---- S5: FF2 split-K=8 partial GEMMs (224 items, K=128 each) ----
    for (int it = b; it < 224; it += NB) {
        int t = it;
        int nt = t & 1; t >>= 1;
        int mt = t % 7; t /= 7;
        int s = t & 1, ks = t >> 1;      // ks 0..7
        gemm_tile(g_hid[s], HIDD, NTOK, p.W2[s], EMBD,
                  g_part[ks * 2 + s], EMBD, mt * 32, nt * 128, ks * 128, 128, sm);
    }
    gsync();

    // ---- S6: FF2 reduce + bias + residual + pixel-shuffle to d_out ----
    for (int r = b; r < 2 * NTOK; r += NB) {
        int s = r >= NTOK;
        int n = s ? r - NTOK : r;
        int idx = n * EMBD + tid;
        float v = 0.f;
        #pragma unroll
        for (int ks = 0; ks < 8; ks++) v += g_part[ks * 2 + s][idx];
        v += p.b2[s][tid] + g_l[s][idx];
        int i = n / 14, j = n % 14;
        int pp = tid >> 4, q = tid & 15;
        int ch = s ? 0 : 1;
        p.out[ch * 50176 + pp * 3136 + q * 196 + i * 14 + j] = v;
    }
}

// ---------------- launch ----------------
extern "C" void kernel_launch(void* const* d_in, const int* in_sizes, int n_in,
                              void* d_out, int out_size)
{
    Params pr;
    pr.vis = (const float*)d_in[0];
    pr.ir  = (const float*)d_in[1];
    pr.ln1w[0] = (const float*)d_in[2];  pr.ln1b[0] = (const float*)d_in[3];
    pr.ln1w[1] = (const float*)d_in[4];  pr.ln1b[1] = (const float*)d_in[5];
    pr.ln2w[0] = (const float*)d_in[6];  pr.ln2b[0] = (const float*)d_in[7];
    pr.ln2w[1] = (const float*)d_in[8];  pr.ln2b[1] = (const float*)d_in[9];
    pr.Wqkv[0] = (const float*)d_in[10]; pr.bqkv[0] = (const float*)d_in[11];
    pr.Wqkv[1] = (const float*)d_in[12]; pr.bqkv[1] = (const float*)d_in[13];
    pr.Wp[0]   = (const float*)d_in[14]; pr.bp[0]   = (const float*)d_in[15];
    pr.Wp[1]   = (const float*)d_in[16]; pr.bp[1]   = (const float*)d_in[17];
    pr.W1[0]   = (const float*)d_in[18]; pr.b1[0]   = (const float*)d_in[19];
    pr.W2[0]   = (const float*)d_in[20]; pr.b2[0]   = (const float*)d_in[21];
    pr.W1[1]   = (const float*)d_in[22]; pr.b1[1]   = (const float*)d_in[23];
    pr.W2[1]   = (const float*)d_in[24]; pr.b2[1]   = (const float*)d_in[25];
    pr.out = (float*)d_out;

    cudaFuncSetAttribute(fused, cudaFuncAttributeMaxDynamicSharedMemorySize,
                         SMEM_BYTES);
    fused<<<NB, NTHR, SMEM_BYTES>>>(pr);
}

// round 8
// speedup vs baseline: 1.7784x; 1.7784x over previous
#include <cuda_runtime.h>
#include <math.h>

#define NTOK 196
#define EMBD 256
#define HIDD 1024
#define NH   8
#define DHD  32
#define NB   296
#define NTHR 256

// ---------------- scratch (allocation-free: __device__ globals) ----------------
__device__ float g_part[16][NTOK * EMBD]; // split-K partials (proj / FF2)
__device__ float g_nrm1[2][NTOK * EMBD];  // LN1 outputs (residual base)
__device__ float g_q[2][NH][NTOK * DHD];  // deinterleaved Q  [n][d]
__device__ float g_k[2][NH][DHD * 200];   // deinterleaved K  [d][n] (pad 200)
__device__ float g_v[2][NH][NTOK * DHD];  // deinterleaved V  [n][d]
__device__ float g_attn[2][NTOK * EMBD];  // attention output
__device__ float g_l[2][NTOK * EMBD];     // LN2 outputs
__device__ float g_hid[2][NTOK * HIDD];   // FF hidden (post-GELU)
__device__ unsigned g_count = 0;
__device__ unsigned g_gen = 0;

// ---------------- grid-wide barrier (all NB blocks co-resident) ----------------
__device__ __forceinline__ void gsync()
{
    __syncthreads();
    if (threadIdx.x == 0) {
        __threadfence();
        unsigned gen = *(volatile unsigned*)&g_gen;
        if (atomicAdd(&g_count, 1u) == NB - 1u) {
            g_count = 0u;
            __threadfence();
            atomicAdd(&g_gen, 1u);
        } else {
            while (*(volatile unsigned*)&g_gen == gen) __nanosleep(32);
        }
        __threadfence();
    }
    __syncthreads();
}

// ---------------- packed fp32x2 FMA helpers ----------------
__device__ __forceinline__ void ffma2(unsigned long long& acc,
                                      unsigned long long a, unsigned long long b)
{
    asm("fma.rn.f32x2 %0, %1, %2, %0;" : "+l"(acc) : "l"(a), "l"(b));
}
__device__ __forceinline__ unsigned long long pk2(float x, float y)
{
    unsigned long long r;
    asm("mov.b64 %0, {%1, %2};" : "=l"(r) : "f"(x), "f"(y));
    return r;
}
__device__ __forceinline__ float2 up2(unsigned long long v)
{
    float2 r;
    asm("mov.b64 {%0, %1}, %2;" : "=f"(r.x), "=f"(r.y) : "l"(v));
    return r;
}

// ---------------- 64x128 GEMM mainloop, 4x8 microtile, f32x2 accum ------------
__device__ __forceinline__ void gemm_main(
    const float* __restrict__ A, int lda, int M,
    const float* __restrict__ B, int ldb,
    int row0, int col0, int kstart, int klen, float* sm,
    unsigned long long (&acc)[4][4])
{
    float (*As)[68] = (float(*)[68])sm;              // [16][68] padded
    float* Bs = sm + 16 * 68;                        // [16][128] flat

    int tid = threadIdx.x;
    int tx = tid & 15, ty = tid >> 4;

    #pragma unroll
    for (int i = 0; i < 4; i++)
        #pragma unroll
        for (int j = 0; j < 4; j++) acc[i][j] = 0ull;

    int ar = tid >> 2, ak = (tid & 3) * 4;           // A loader
    bool avalid = (row0 + ar) < M;
    const float* Arow = A + (row0 + ar) * lda + kstart + ak;
    int brow = tid >> 5, bcol = (tid * 4) & 127;     // B loader

    for (int k0 = 0; k0 < klen; k0 += 16) {
        float4 av = make_float4(0.f, 0.f, 0.f, 0.f);
        if (avalid) av = *(const float4*)(Arow + k0);
        As[ak + 0][ar] = av.x; As[ak + 1][ar] = av.y;
        As[ak + 2][ar] = av.z; As[ak + 3][ar] = av.w;

        const float* Bb = B + (kstart + k0) * ldb + col0;
        *(float4*)&Bs[brow * 128 + bcol] =
            *(const float4*)&Bb[brow * ldb + bcol];
        *(float4*)&Bs[(brow + 8) * 128 + bcol] =
            *(const float4*)&Bb[(brow + 8) * ldb + bcol];
        __syncthreads();

        #pragma unroll
        for (int k = 0; k < 16; k++) {
            float4 a = *(float4*)&As[k][ty * 4];
            ulonglong2 b01 = *(ulonglong2*)&Bs[k * 128 + tx * 8];
            ulonglong2 b23 = *(ulonglong2*)&Bs[k * 128 + tx * 8 + 4];
            unsigned long long a0 = pk2(a.x, a.x), a1 = pk2(a.y, a.y);
            unsigned long long a2 = pk2(a.z, a.z), a3 = pk2(a.w, a.w);
            ffma2(acc[0][0], a0, b01.x); ffma2(acc[0][1], a0, b01.y);
            ffma2(acc[0][2], a0, b23.x); ffma2(acc[0][3], a0, b23.y);
            ffma2(acc[1][0], a1, b01.x); ffma2(acc[1][1], a1, b01.y);
            ffma2(acc[1][2], a1, b23.x); ffma2(acc[1][3], a1, b23.y);
            ffma2(acc[2][0], a2, b01.x); ffma2(acc[2][1], a2, b01.y);
            ffma2(acc[2][2], a2, b23.x); ffma2(acc[2][3], a2, b23.y);
            ffma2(acc[3][0], a3, b01.x); ffma2(acc[3][1], a3, b01.y);
            ffma2(acc[3][2], a3, b23.x); ffma2(acc[3][3], a3, b23.y);
        }
        __syncthreads();
    }
}

// unpack one acc row into 8 floats
__device__ __forceinline__ void unpack_row(unsigned long long (&acc)[4][4],
                                           int i, float* v)
{
    float2 v0 = up2(acc[i][0]), v1 = up2(acc[i][1]);
    float2 v2 = up2(acc[i][2]), v3 = up2(acc[i][3]);
    v[0] = v0.x; v[1] = v0.y; v[2] = v1.x; v[3] = v1.y;
    v[4] = v2.x; v[5] = v2.y; v[6] = v3.x; v[7] = v3.y;
}

// ---------------- block LayerNorm over 256-elem row (256 threads) -------------
__device__ __forceinline__ float ln_norm(float v, float w, float b, float* red)
{
    int tid = threadIdx.x;
    float t = v;
    #pragma unroll
    for (int off = 16; off; off >>= 1) t += __shfl_xor_sync(0xffffffffu, t, off);
    __syncthreads();
    if ((tid & 31) == 0) red[tid >> 5] = t;
    __syncthreads();
    float mean = (red[0] + red[1] + red[2] + red[3] +
                  red[4] + red[5] + red[6] + red[7]) * (1.0f / EMBD);
    float d = v - mean;
    t = d * d;
    #pragma unroll
    for (int off = 16; off; off >>= 1) t += __shfl_xor_sync(0xffffffffu, t, off);
    __syncthreads();
    if ((tid & 31) == 0) red[tid >> 5] = t;
    __syncthreads();
    float var = (red[0] + red[1] + red[2] + red[3] +
                 red[4] + red[5] + red[6] + red[7]) * (1.0f / EMBD);
    return d * rsqrtf(var + 1e-5f) * w + b;
}

// ---------------- attention smem layout (floats) ----------------
#define A_KS 0
#define A_VS (32 * 200)
#define A_SS (A_VS + NTOK * DHD)
#define A_QS (A_SS + 32 * 200)
#define A_IV (A_QS + 32 * 32)
#define SMEM_FLOATS (A_IV + 32)
#define SMEM_BYTES  (SMEM_FLOATS * 4)

__device__ void attn_tile(int qt, int h, int s, float* buf)
{
    float (*Ks)[200] = (float(*)[200])(buf + A_KS);
    float (*Vs)[DHD] = (float(*)[DHD])(buf + A_VS);
    float (*Ss)[200] = (float(*)[200])(buf + A_SS);
    float (*Qs)[DHD] = (float(*)[DHD])(buf + A_QS);
    float* inv = buf + A_IV;
    int tid = threadIdx.x;

    const float* gk = g_k[1 - s][h];
    const float* gv = g_v[1 - s][h];
    const float* gq = g_q[s][h];

    for (int i = tid; i < 32 * 50; i += NTHR)
        ((float4*)(buf + A_KS))[i] = ((const float4*)gk)[i];
    for (int i = tid; i < NTOK * 8; i += NTHR)
        ((float4*)(buf + A_VS))[i] = ((const float4*)gv)[i];
    for (int i = tid; i < 32 * 8; i += NTHR) {
        int q = i >> 3, d4 = (i & 7) << 2;
        int qg = qt * 32 + q;
        float4 v = make_float4(0.f, 0.f, 0.f, 0.f);
        if (qg < NTOK) v = *(const float4*)&gq[qg * DHD + d4];
        *(float4*)&Qs[q][d4] = v;
    }
    __syncthreads();

    // scores
    {
        int q = tid >> 3, g = tid & 7;
        float qr[32];
        #pragma unroll
        for (int d = 0; d < 32; d++) qr[d] = Qs[q][d];
        #pragma unroll
        for (int kk = 0; kk < 7; kk++) {
            int j0 = g * 4 + kk * 32;
            if (j0 >= NTOK) break;
            float a0 = 0.f, a1 = 0.f, a2 = 0.f, a3 = 0.f;
            #pragma unroll
            for (int d = 0; d < 32; d++) {
                float4 kv = *(float4*)&Ks[d][j0];
                a0 += qr[d] * kv.x; a1 += qr[d] * kv.y;
                a2 += qr[d] * kv.z; a3 += qr[d] * kv.w;
            }
            Ss[q][j0 + 0] = a0 * 0.0625f;
            Ss[q][j0 + 1] = a1 * 0.0625f;
            Ss[q][j0 + 2] = a2 * 0.0625f;
            Ss[q][j0 + 3] = a3 * 0.0625f;
        }
    }
    __syncthreads();

    // softmax
    {
        int w = tid >> 5, lane = tid & 31;
        for (int r = 0; r < 4; r++) {
            int q = w * 4 + r;
            float m = -1e30f;
            for (int j = lane; j < NTOK; j += 32) m = fmaxf(m, Ss[q][j]);
            #pragma unroll
            for (int off = 16; off; off >>= 1)
                m = fmaxf(m, __shfl_xor_sync(0xffffffffu, m, off));
            float sum = 0.f;
            for (int j = lane; j < NTOK; j += 32) {
                float e = __expf(Ss[q][j] - m);
                Ss[q][j] = e;
                sum += e;
            }
            #pragma unroll
            for (int off = 16; off; off >>= 1)
                sum += __shfl_xor_sync(0xffffffffu, sum, off);
            if (lane == 0) inv[q] = 1.0f / sum;
        }
    }
    __syncthreads();

    // PV
    {
        int q = tid >> 3, d0 = (tid & 7) * 4;
        float4 acc = make_float4(0.f, 0.f, 0.f, 0.f);
        for (int j = 0; j < NTOK; j += 2) {
            float p0 = Ss[q][j], p1 = Ss[q][j + 1];
            float4 v0 = *(float4*)&Vs[j][d0];
            float4 v1 = *(float4*)&Vs[j + 1][d0];
            acc.x += p0 * v0.x + p1 * v1.x;
            acc.y += p0 * v0.y + p1 * v1.y;
            acc.z += p0 * v0.z + p1 * v1.z;
            acc.w += p0 * v0.w + p1 * v1.w;
        }
        float iv = inv[q];
        acc.x *= iv; acc.y *= iv; acc.z *= iv; acc.w *= iv;
        int qg = qt * 32 + q;
        if (qg < NTOK)
            *(float4*)&g_attn[s][qg * EMBD + h * DHD + d0] = acc;
    }
}

// ---------------- fused persistent kernel ----------------
struct Params {
    const float *vis, *ir;
    const float *ln1w[2], *ln1b[2], *ln2w[2], *ln2b[2];
    const float *Wqkv[2], *bqkv[2], *Wp[2], *bp[2];
    const float *W1[2], *b1[2], *W2[2], *b2[2];
    float* out;
};

__global__ void __launch_bounds__(NTHR, 2) fused(Params p)
{
    extern __shared__ float sm[];
    int b = blockIdx.x;
    int tid = threadIdx.x;
    int tx = tid & 15, ty = tid >> 4;
    unsigned long long acc[4][4];

    // ---- S0: QKV GEMM K=256 (48 items) w/ fused bias + deinterleave epilogue,
    //          LN1 on the remaining 248 blocks ----
    if (b < 48) {
        int t = b;
        int nt = t % 6; t /= 6;
        int mt = t % 4; t /= 4;
        int s = t;
        int row0 = mt * 64, col0 = nt * 128;
        gemm_main(s ? p.ir : p.vis, EMBD, NTOK, p.Wqkv[s], 768,
                  row0, col0, 0, 256, sm, acc);
        const float* bq = p.bqkv[s];
        #pragma unroll
        for (int i = 0; i < 4; i++) {
            int n = row0 + ty * 4 + i;
            if (n < NTOK) {
                float v[8];
                unpack_row(acc, i, v);
                #pragma unroll
                for (int j = 0; j < 8; j++) {
                    int c = col0 + tx * 8 + j;
                    float val = v[j] + bq[c];
                    int hd = c / 3, t3 = c - hd * 3;
                    int h = hd >> 5, d = hd & 31;
                    if (t3 == 0)      g_q[s][h][n * DHD + d] = val;
                    else if (t3 == 1) g_k[s][h][d * 200 + n] = val;
                    else              g_v[s][h][n * DHD + d] = val;
                }
            }
        }
    } else {
        for (int r = b - 48; r < 2 * NTOK; r += NB - 48) {
            int s = r >= NTOK;
            int n = s ? r - NTOK : r;
            float v = (s ? p.ir : p.vis)[n * EMBD + tid];
            g_nrm1[s][n * EMBD + tid] =
                ln_norm(v, p.ln1w[s][tid], p.ln1b[s][tid], sm);
        }
    }
    gsync();

    // ---- S1: cross attention (112 items) ----
    if (b < 112) {
        int t = b;
        int qt = t % 7; t /= 7;
        int h = t % 8;
        int s = t / 8;
        attn_tile(qt, h, s, sm);
    }
    gsync();

    // ---- S2: proj split-K=4 partial GEMMs (64 items, K=64 each) ----
    if (b < 64) {
        int t = b;
        int nt = t & 1; t >>= 1;
        int mt = t & 3; t >>= 2;
        int s = t & 1, ks = t >> 1;
        int row0 = mt * 64, col0 = nt * 128;
        gemm_main(g_attn[s], EMBD, NTOK, p.Wp[s], EMBD,
                  row0, col0, ks * 64, 64, sm, acc);
        float* Cp = g_part[ks * 2 + s];
        #pragma unroll
        for (int i = 0; i < 4; i++) {
            int r = row0 + ty * 4 + i;
            if (r < NTOK) {
                float v[8];
                unpack_row(acc, i, v);
                *(float4*)&Cp[r * EMBD + col0 + tx * 8]     = *(float4*)&v[0];
                *(float4*)&Cp[r * EMBD + col0 + tx * 8 + 4] = *(float4*)&v[4];
            }
        }
    }
    gsync();

    // ---- S3: proj reduce + bias + residual + LN2 ----
    for (int r = b; r < 2 * NTOK; r += NB) {
        int s = r >= NTOK;
        int n = s ? r - NTOK : r;
        int idx = n * EMBD + tid;
        float v = g_part[s][idx] + g_part[2 + s][idx] +
                  g_part[4 + s][idx] + g_part[6 + s][idx] +
                  p.bp[s][tid] + g_nrm1[s][idx];
        g_l[s][idx] = ln_norm(v, p.ln2w[s][tid], p.ln2b[s][tid], sm);
    }
    gsync();

    // ---- S4: FF1 GEMM K=256 (64 items) w/ fused bias + exact GELU ----
    if (b < 64) {
        int t = b;
        int nt = t & 7; t >>= 3;
        int mt = t & 3; t >>= 2;
        int s = t;
        int row0 = mt * 64, col0 = nt * 128;
        gemm_main(g_l[s], EMBD, NTOK, p.W1[s], HIDD,
                  row0, col0, 0, 256, sm, acc);
        const float* b1 = p.b1[s];
        #pragma unroll
        for (int i = 0; i < 4; i++) {
            int r = row0 + ty * 4 + i;
            if (r < NTOK) {
                float v[8];
                unpack_row(acc, i, v);
                #pragma unroll
                for (int j = 0; j < 8; j++) {
                    float x = v[j] + b1[col0 + tx * 8 + j];
                    v[j] = 0.5f * x * (1.0f + erff(x * 0.70710678118654752f));
                }
                float* Cp = &g_hid[s][r * HIDD + col0 + tx * 8];
                *(float4*)&Cp[0] = *(float4*)&v[0];
                *(float4*)&Cp[4] = *(float4*)&v[4];
            }
        }
    }
    gsync();

    // ---- S5: FF2 split-K=8 partial GEMMs (128 items, K=128 each) ----
    if (b < 128) {
        int t = b;
        int nt = t & 1; t >>= 1;
        int mt = t & 3; t >>= 2;
        int s = t & 1, ks = t >> 1;      // ks 0..7
        int row0 = mt * 64, col0 = nt * 128;
        gemm_main(g_hid[s], HIDD, NTOK, p.W2[s], EMBD,
                  row0, col0, ks * 128, 128, sm, acc);
        float* Cp = g_part[ks * 2 + s];
        #pragma unroll
        for (int i = 0; i < 4; i++) {
            int r = row0 + ty * 4 + i;
            if (r < NTOK) {
                float v[8];
                unpack_row(acc, i, v);
                *(float4*)&Cp[r * EMBD + col0 + tx * 8]     = *(float4*)&v[0];
                *(float4*)&Cp[r * EMBD + col0 + tx * 8 + 4] = *(float4*)&v[4];
            }
        }
    }
    gsync();

    // ---- S6: FF2 reduce + bias + residual + pixel-shuffle to d_out ----
    for (int r = b; r < 2 * NTOK; r += NB) {
        int s = r >= NTOK;
        int n = s ? r - NTOK : r;
        int idx = n * EMBD + tid;
        float v = 0.f;
        #pragma unroll
        for (int ks = 0; ks < 8; ks++) v += g_part[ks * 2 + s][idx];
        v += p.b2[s][tid] + g_l[s][idx];
        int i = n / 14, j = n % 14;
        int pp = tid >> 4, q = tid & 15;
        int ch = s ? 0 : 1;
        p.out[ch * 50176 + pp * 3136 + q * 196 + i * 14 + j] = v;
    }
}

// ---------------- launch ----------------
extern "C" void kernel_launch(void* const* d_in, const int* in_sizes, int n_in,
                              void* d_out, int out_size)
{
    Params pr;
    pr.vis = (const float*)d_in[0];
    pr.ir  = (const float*)d_in[1];
    pr.ln1w[0] = (const float*)d_in[2];  pr.ln1b[0] = (const float*)d_in[3];
    pr.ln1w[1] = (const float*)d_in[4];  pr.ln1b[1] = (const float*)d_in[5];
    pr.ln2w[0] = (const float*)d_in[6];  pr.ln2b[0] = (const float*)d_in[7];
    pr.ln2w[1] = (const float*)d_in[8];  pr.ln2b[1] = (const float*)d_in[9];
    pr.Wqkv[0] = (const float*)d_in[10]; pr.bqkv[0] = (const float*)d_in[11];
    pr.Wqkv[1] = (const float*)d_in[12]; pr.bqkv[1] = (const float*)d_in[13];
    pr.Wp[0]   = (const float*)d_in[14]; pr.bp[0]   = (const float*)d_in[15];
    pr.Wp[1]   = (const float*)d_in[16]; pr.bp[1]   = (const float*)d_in[17];
    pr.W1[0]   = (const float*)d_in[18]; pr.b1[0]   = (const float*)d_in[19];
    pr.W2[0]   = (const float*)d_in[20]; pr.b2[0]   = (const float*)d_in[21];
    pr.W1[1]   = (const float*)d_in[22]; pr.b1[1]   = (const float*)d_in[23];
    pr.W2[1]   = (const float*)d_in[24]; pr.b2[1]   = (const float*)d_in[25];
    pr.out = (float*)d_out;

    cudaFuncSetAttribute(fused, cudaFuncAttributeMaxDynamicSharedMemorySize,
                         SMEM_BYTES);
    fused<<<NB, NTHR, SMEM_BYTES>>>(pr);
}

// round 9
// speedup vs baseline: 1.8479x; 1.0391x over previous
#include <cuda_runtime.h>
#include <math.h>

#define NTOK 196
#define EMBD 256
#define HIDD 1024
#define NH   8
#define DHD  32
#define NB   296
#define NTHR 256

// ---------------- scratch (allocation-free: __device__ globals) ----------------
__device__ float g_part[16][NTOK * EMBD]; // split-K partials (proj / FF2)
__device__ float g_nrm1[2][NTOK * EMBD];  // LN1 outputs (residual base)
__device__ float g_q[2][NH][NTOK * DHD];  // deinterleaved Q  [n][d]
__device__ float g_k[2][NH][DHD * 200];   // deinterleaved K  [d][n] (pad 200)
__device__ float g_v[2][NH][NTOK * DHD];  // deinterleaved V  [n][d]
__device__ float g_attn[2][NTOK * EMBD];  // attention output
__device__ float g_l[2][NTOK * EMBD];     // LN2 outputs
__device__ float g_hid[2][NTOK * HIDD];   // FF hidden (post-GELU)
__device__ unsigned g_count = 0;
__device__ unsigned g_gen = 0;

// ---------------- grid-wide barrier (all NB blocks co-resident) ----------------
__device__ __forceinline__ void gsync()
{
    __syncthreads();
    if (threadIdx.x == 0) {
        __threadfence();
        unsigned gen = *(volatile unsigned*)&g_gen;
        if (atomicAdd(&g_count, 1u) == NB - 1u) {
            g_count = 0u;
            __threadfence();
            atomicAdd(&g_gen, 1u);
        } else {
            while (*(volatile unsigned*)&g_gen == gen) { }
        }
        __threadfence();
    }
    __syncthreads();
}

// ---------------- packed fp32x2 FMA helpers ----------------
__device__ __forceinline__ void ffma2(unsigned long long& acc,
                                      unsigned long long a, unsigned long long b)
{
    asm("fma.rn.f32x2 %0, %1, %2, %0;" : "+l"(acc) : "l"(a), "l"(b));
}
__device__ __forceinline__ unsigned long long pk2(float x, float y)
{
    unsigned long long r;
    asm("mov.b64 %0, {%1, %2};" : "=l"(r) : "f"(x), "f"(y));
    return r;
}
__device__ __forceinline__ float2 up2(unsigned long long v)
{
    float2 r;
    asm("mov.b64 {%0, %1}, %2;" : "=f"(r.x), "=f"(r.y) : "l"(v));
    return r;
}

// ---------------- 64x64 GEMM mainloop, 4x4 microtile, f32x2 accum -------------
// acc[i][0..1] hold cols tx*4 .. tx*4+3 for row ty*4+i.
__device__ __forceinline__ void gemm_main(
    const float* __restrict__ A, int lda, int M,
    const float* __restrict__ B, int ldb,
    int row0, int col0, int kstart, int klen, float* sm,
    unsigned long long (&acc)[4][2])
{
    float (*As)[68] = (float(*)[68])sm;              // [16][68] padded
    float (*Bs)[68] = (float(*)[68])(sm + 16 * 68);  // [16][68] padded

    int tid = threadIdx.x;
    int tx = tid & 15, ty = tid >> 4;

    #pragma unroll
    for (int i = 0; i < 4; i++) {
        acc[i][0] = 0ull; acc[i][1] = 0ull;
    }

    int ar = tid >> 2, ak = (tid & 3) * 4;           // A loader: 64 rows x 16 k
    bool avalid = (row0 + ar) < M;
    const float* Arow = A + (row0 + ar) * lda + kstart + ak;
    int brow = tid >> 4, bcol = (tid & 15) * 4;      // B loader: 16 k x 64 n

    for (int k0 = 0; k0 < klen; k0 += 16) {
        float4 av = make_float4(0.f, 0.f, 0.f, 0.f);
        if (avalid) av = *(const float4*)(Arow + k0);
        As[ak + 0][ar] = av.x; As[ak + 1][ar] = av.y;
        As[ak + 2][ar] = av.z; As[ak + 3][ar] = av.w;

        *(float4*)&Bs[brow][bcol] =
            *(const float4*)&B[(kstart + k0 + brow) * ldb + col0 + bcol];
        __syncthreads();

        #pragma unroll
        for (int k = 0; k < 16; k++) {
            float4 a = *(float4*)&As[k][ty * 4];
            ulonglong2 b = *(ulonglong2*)&Bs[k][tx * 4];
            unsigned long long a0 = pk2(a.x, a.x), a1 = pk2(a.y, a.y);
            unsigned long long a2 = pk2(a.z, a.z), a3 = pk2(a.w, a.w);
            ffma2(acc[0][0], a0, b.x); ffma2(acc[0][1], a0, b.y);
            ffma2(acc[1][0], a1, b.x); ffma2(acc[1][1], a1, b.y);
            ffma2(acc[2][0], a2, b.x); ffma2(acc[2][1], a2, b.y);
            ffma2(acc[3][0], a3, b.x); ffma2(acc[3][1], a3, b.y);
        }
        __syncthreads();
    }
}

// unpack one acc row into 4 floats
__device__ __forceinline__ void unpack_row(unsigned long long (&acc)[4][2],
                                           int i, float* v)
{
    float2 v0 = up2(acc[i][0]), v1 = up2(acc[i][1]);
    v[0] = v0.x; v[1] = v0.y; v[2] = v1.x; v[3] = v1.y;
}

// ---------------- block LayerNorm over 256-elem row (256 threads) -------------
__device__ __forceinline__ float ln_norm(float v, float w, float b, float* red)
{
    int tid = threadIdx.x;
    float t = v;
    #pragma unroll
    for (int off = 16; off; off >>= 1) t += __shfl_xor_sync(0xffffffffu, t, off);
    __syncthreads();
    if ((tid & 31) == 0) red[tid >> 5] = t;
    __syncthreads();
    float mean = (red[0] + red[1] + red[2] + red[3] +
                  red[4] + red[5] + red[6] + red[7]) * (1.0f / EMBD);
    float d = v - mean;
    t = d * d;
    #pragma unroll
    for (int off = 16; off; off >>= 1) t += __shfl_xor_sync(0xffffffffu, t, off);
    __syncthreads();
    if ((tid & 31) == 0) red[tid >> 5] = t;
    __syncthreads();
    float var = (red[0] + red[1] + red[2] + red[3] +
                 red[4] + red[5] + red[6] + red[7]) * (1.0f / EMBD);
    return d * rsqrtf(var + 1e-5f) * w + b;
}

// ---------------- attention smem layout (floats) ----------------
#define A_KS 0
#define A_VS (32 * 200)
#define A_SS (A_VS + NTOK * DHD)
#define A_QS (A_SS + 32 * 200)
#define A_IV (A_QS + 32 * 32)
#define SMEM_FLOATS (A_IV + 32)
#define SMEM_BYTES  (SMEM_FLOATS * 4)

__device__ void attn_tile(int qt, int h, int s, float* buf)
{
    float (*Ks)[200] = (float(*)[200])(buf + A_KS);
    float (*Vs)[DHD] = (float(*)[DHD])(buf + A_VS);
    float (*Ss)[200] = (float(*)[200])(buf + A_SS);
    float (*Qs)[DHD] = (float(*)[DHD])(buf + A_QS);
    float* inv = buf + A_IV;
    int tid = threadIdx.x;

    const float* gk = g_k[1 - s][h];
    const float* gv = g_v[1 - s][h];
    const float* gq = g_q[s][h];

    for (int i = tid; i < 32 * 50; i += NTHR)
        ((float4*)(buf + A_KS))[i] = ((const float4*)gk)[i];
    for (int i = tid; i < NTOK * 8; i += NTHR)
        ((float4*)(buf + A_VS))[i] = ((const float4*)gv)[i];
    for (int i = tid; i < 32 * 8; i += NTHR) {
        int q = i >> 3, d4 = (i & 7) << 2;
        int qg = qt * 32 + q;
        float4 v = make_float4(0.f, 0.f, 0.f, 0.f);
        if (qg < NTOK) v = *(const float4*)&gq[qg * DHD + d4];
        *(float4*)&Qs[q][d4] = v;
    }
    __syncthreads();

    // scores
    {
        int q = tid >> 3, g = tid & 7;
        float qr[32];
        #pragma unroll
        for (int d = 0; d < 32; d++) qr[d] = Qs[q][d];
        #pragma unroll
        for (int kk = 0; kk < 7; kk++) {
            int j0 = g * 4 + kk * 32;
            if (j0 >= NTOK) break;
            float a0 = 0.f, a1 = 0.f, a2 = 0.f, a3 = 0.f;
            #pragma unroll
            for (int d = 0; d < 32; d++) {
                float4 kv = *(float4*)&Ks[d][j0];
                a0 += qr[d] * kv.x; a1 += qr[d] * kv.y;
                a2 += qr[d] * kv.z; a3 += qr[d] * kv.w;
            }
            Ss[q][j0 + 0] = a0 * 0.0625f;
            Ss[q][j0 + 1] = a1 * 0.0625f;
            Ss[q][j0 + 2] = a2 * 0.0625f;
            Ss[q][j0 + 3] = a3 * 0.0625f;
        }
    }
    __syncthreads();

    // softmax
    {
        int w = tid >> 5, lane = tid & 31;
        for (int r = 0; r < 4; r++) {
            int q = w * 4 + r;
            float m = -1e30f;
            for (int j = lane; j < NTOK; j += 32) m = fmaxf(m, Ss[q][j]);
            #pragma unroll
            for (int off = 16; off; off >>= 1)
                m = fmaxf(m, __shfl_xor_sync(0xffffffffu, m, off));
            float sum = 0.f;
            for (int j = lane; j < NTOK; j += 32) {
                float e = __expf(Ss[q][j] - m);
                Ss[q][j] = e;
                sum += e;
            }
            #pragma unroll
            for (int off = 16; off; off >>= 1)
                sum += __shfl_xor_sync(0xffffffffu, sum, off);
            if (lane == 0) inv[q] = 1.0f / sum;
        }
    }
    __syncthreads();

    // PV
    {
        int q = tid >> 3, d0 = (tid & 7) * 4;
        float4 acc = make_float4(0.f, 0.f, 0.f, 0.f);
        for (int j = 0; j < NTOK; j += 2) {
            float p0 = Ss[q][j], p1 = Ss[q][j + 1];
            float4 v0 = *(float4*)&Vs[j][d0];
            float4 v1 = *(float4*)&Vs[j + 1][d0];
            acc.x += p0 * v0.x + p1 * v1.x;
            acc.y += p0 * v0.y + p1 * v1.y;
            acc.z += p0 * v0.z + p1 * v1.z;
            acc.w += p0 * v0.w + p1 * v1.w;
        }
        float iv = inv[q];
        acc.x *= iv; acc.y *= iv; acc.z *= iv; acc.w *= iv;
        int qg = qt * 32 + q;
        if (qg < NTOK)
            *(float4*)&g_attn[s][qg * EMBD + h * DHD + d0] = acc;
    }
}

// ---------------- fused persistent kernel ----------------
struct Params {
    const float *vis, *ir;
    const float *ln1w[2], *ln1b[2], *ln2w[2], *ln2b[2];
    const float *Wqkv[2], *bqkv[2], *Wp[2], *bp[2];
    const float *W1[2], *b1[2], *W2[2], *b2[2];
    float* out;
};

__global__ void __launch_bounds__(NTHR, 2) fused(Params p)
{
    extern __shared__ float sm[];
    int b = blockIdx.x;
    int tid = threadIdx.x;
    int tx = tid & 15, ty = tid >> 4;
    unsigned long long acc[4][2];

    // ---- S0: QKV GEMM K=256 (96 items, 64x64) w/ fused bias + deinterleave,
    //          LN1 on the remaining 200 blocks ----
    if (b < 96) {
        int t = b;
        int nt = t % 12; t /= 12;
        int mt = t % 4; t /= 4;
        int s = t;
        int row0 = mt * 64, col0 = nt * 64;
        gemm_main(s ? p.ir : p.vis, EMBD, NTOK, p.Wqkv[s], 768,
                  row0, col0, 0, 256, sm, acc);
        const float* bq = p.bqkv[s];
        #pragma unroll
        for (int i = 0; i < 4; i++) {
            int n = row0 + ty * 4 + i;
            if (n < NTOK) {
                float v[4];
                unpack_row(acc, i, v);
                #pragma unroll
                for (int j = 0; j < 4; j++) {
                    int c = col0 + tx * 4 + j;
                    float val = v[j] + bq[c];
                    int hd = c / 3, t3 = c - hd * 3;
                    int h = hd >> 5, d = hd & 31;
                    if (t3 == 0)      g_q[s][h][n * DHD + d] = val;
                    else if (t3 == 1) g_k[s][h][d * 200 + n] = val;
                    else              g_v[s][h][n * DHD + d] = val;
                }
            }
        }
    } else {
        for (int r = b - 96; r < 2 * NTOK; r += NB - 96) {
            int s = r >= NTOK;
            int n = s ? r - NTOK : r;
            float v = (s ? p.ir : p.vis)[n * EMBD + tid];
            g_nrm1[s][n * EMBD + tid] =
                ln_norm(v, p.ln1w[s][tid], p.ln1b[s][tid], sm);
        }
    }
    gsync();

    // ---- S1: cross attention (112 items) ----
    if (b < 112) {
        int t = b;
        int qt = t % 7; t /= 7;
        int h = t % 8;
        int s = t / 8;
        attn_tile(qt, h, s, sm);
    }
    gsync();

    // ---- S2: proj split-K=4 partial GEMMs (128 items, 64x64, K=64) ----
    if (b < 128) {
        int t = b;
        int nt = t & 3; t >>= 2;
        int mt = t & 3; t >>= 2;
        int s = t & 1, ks = t >> 1;
        int row0 = mt * 64, col0 = nt * 64;
        gemm_main(g_attn[s], EMBD, NTOK, p.Wp[s], EMBD,
                  row0, col0, ks * 64, 64, sm, acc);
        float* Cp = g_part[ks * 2 + s];
        #pragma unroll
        for (int i = 0; i < 4; i++) {
            int r = row0 + ty * 4 + i;
            if (r < NTOK) {
                float v[4];
                unpack_row(acc, i, v);
                *(float4*)&Cp[r * EMBD + col0 + tx * 4] = *(float4*)&v[0];
            }
        }
    }
    gsync();

    // ---- S3: proj reduce + bias + residual + LN2 ----
    for (int r = b; r < 2 * NTOK; r += NB) {
        int s = r >= NTOK;
        int n = s ? r - NTOK : r;
        int idx = n * EMBD + tid;
        float v = g_part[s][idx] + g_part[2 + s][idx] +
                  g_part[4 + s][idx] + g_part[6 + s][idx] +
                  p.bp[s][tid] + g_nrm1[s][idx];
        g_l[s][idx] = ln_norm(v, p.ln2w[s][tid], p.ln2b[s][tid], sm);
    }
    gsync();

    // ---- S4: FF1 GEMM K=256 (128 items, 64x64) w/ fused bias + exact GELU ----
    if (b < 128) {
        int t = b;
        int nt = t & 15; t >>= 4;
        int mt = t & 3; t >>= 2;
        int s = t;
        int row0 = mt * 64, col0 = nt * 64;
        gemm_main(g_l[s], EMBD, NTOK, p.W1[s], HIDD,
                  row0, col0, 0, 256, sm, acc);
        const float* b1 = p.b1[s];
        #pragma unroll
        for (int i = 0; i < 4; i++) {
            int r = row0 + ty * 4 + i;
            if (r < NTOK) {
                float v[4];
                unpack_row(acc, i, v);
                #pragma unroll
                for (int j = 0; j < 4; j++) {
                    float x = v[j] + b1[col0 + tx * 4 + j];
                    v[j] = 0.5f * x * (1.0f + erff(x * 0.70710678118654752f));
                }
                *(float4*)&g_hid[s][r * HIDD + col0 + tx * 4] = *(float4*)&v[0];
            }
        }
    }
    gsync();

    // ---- S5: FF2 split-K=8 partial GEMMs (256 items, 64x64, K=128) ----
    if (b < 256) {
        int t = b;
        int nt = t & 3; t >>= 2;
        int mt = t & 3; t >>= 2;
        int s = t & 1, ks = t >> 1;      // ks 0..7
        int row0 = mt * 64, col0 = nt * 64;
        gemm_main(g_hid[s], HIDD, NTOK, p.W2[s], EMBD,
                  row0, col0, ks * 128, 128, sm, acc);
        float* Cp = g_part[ks * 2 + s];
        #pragma unroll
        for (int i = 0; i < 4; i++) {
            int r = row0 + ty * 4 + i;
            if (r < NTOK) {
                float v[4];
                unpack_row(acc, i, v);
                *(float4*)&Cp[r * EMBD + col0 + tx * 4] = *(float4*)&v[0];
            }
        }
    }
    gsync();

    // ---- S6: FF2 reduce + bias + residual + pixel-shuffle to d_out ----
    for (int r = b; r < 2 * NTOK; r += NB) {
        int s = r >= NTOK;
        int n = s ? r - NTOK : r;
        int idx = n * EMBD + tid;
        float v = 0.f;
        #pragma unroll
        for (int ks = 0; ks < 8; ks++) v += g_part[ks * 2 + s][idx];
        v += p.b2[s][tid] + g_l[s][idx];
        int i = n / 14, j = n % 14;
        int pp = tid >> 4, q = tid & 15;
        int ch = s ? 0 : 1;
        p.out[ch * 50176 + pp * 3136 + q * 196 + i * 14 + j] = v;
    }
}

// ---------------- launch ----------------
extern "C" void kernel_launch(void* const* d_in, const int* in_sizes, int n_in,
                              void* d_out, int out_size)
{
    Params pr;
    pr.vis = (const float*)d_in[0];
    pr.ir  = (const float*)d_in[1];
    pr.ln1w[0] = (const float*)d_in[2];  pr.ln1b[0] = (const float*)d_in[3];
    pr.ln1w[1] = (const float*)d_in[4];  pr.ln1b[1] = (const float*)d_in[5];
    pr.ln2w[0] = (const float*)d_in[6];  pr.ln2b[0] = (const float*)d_in[7];
    pr.ln2w[1] = (const float*)d_in[8];  pr.ln2b[1] = (const float*)d_in[9];
    pr.Wqkv[0] = (const float*)d_in[10]; pr.bqkv[0] = (const float*)d_in[11];
    pr.Wqkv[1] = (const float*)d_in[12]; pr.bqkv[1] = (const float*)d_in[13];
    pr.Wp[0]   = (const float*)d_in[14]; pr.bp[0]   = (const float*)d_in[15];
    pr.Wp[1]   = (const float*)d_in[16]; pr.bp[1]   = (const float*)d_in[17];
    pr.W1[0]   = (const float*)d_in[18]; pr.b1[0]   = (const float*)d_in[19];
    pr.W2[0]   = (const float*)d_in[20]; pr.b2[0]   = (const float*)d_in[21];
    pr.W1[1]   = (const float*)d_in[22]; pr.b1[1]   = (const float*)d_in[23];
    pr.W2[1]   = (const float*)d_in[24]; pr.b2[1]   = (const float*)d_in[25];
    pr.out = (float*)d_out;

    cudaFuncSetAttribute(fused, cudaFuncAttributeMaxDynamicSharedMemorySize,
                         SMEM_BYTES);
    fused<<<NB, NTHR, SMEM_BYTES>>>(pr);
}

// round 10
// speedup vs baseline: 2.5202x; 1.3638x over previous
#include <cuda_runtime.h>
#include <math.h>

#define NTOK 196
#define EMBD 256
#define HIDD 1024
#define NH   8
#define DHD  32
#define NB   296
#define NTHR 256

// ---------------- scratch (allocation-free: __device__ globals) ----------------
__device__ float g_part[16][NTOK * EMBD]; // split-K partials (proj / FF2)
__device__ float g_nrm1[2][NTOK * EMBD];  // LN1 outputs (residual base)
__device__ float g_q[2][NH][NTOK * DHD];  // deinterleaved Q  [n][d]
__device__ float g_k[2][NH][DHD * 200];   // deinterleaved K  [d][n] (pad 200)
__device__ float g_v[2][NH][NTOK * DHD];  // deinterleaved V  [n][d]
__device__ float g_attn[2][NTOK * EMBD];  // attention output
__device__ float g_l[2][NTOK * EMBD];     // LN2 outputs
__device__ float g_hid[2][NTOK * HIDD];   // FF hidden (post-GELU)
__device__ unsigned g_count = 0;
__device__ unsigned g_gen = 0;

// ---------------- grid-wide barrier (all NB blocks co-resident) ----------------
__device__ __forceinline__ void gsync()
{
    __syncthreads();
    if (threadIdx.x == 0) {
        __threadfence();
        unsigned gen = *(volatile unsigned*)&g_gen;
        if (atomicAdd(&g_count, 1u) == NB - 1u) {
            g_count = 0u;
            __threadfence();
            atomicAdd(&g_gen, 1u);
        } else {
            while (*(volatile unsigned*)&g_gen == gen) { }
        }
        __threadfence();
    }
    __syncthreads();
}

// ---------------- packed fp32x2 FMA helpers ----------------
__device__ __forceinline__ void ffma2(unsigned long long& acc,
                                      unsigned long long a, unsigned long long b)
{
    asm("fma.rn.f32x2 %0, %1, %2, %0;" : "+l"(acc) : "l"(a), "l"(b));
}
__device__ __forceinline__ float2 up2(unsigned long long v)
{
    float2 r;
    asm("mov.b64 {%0, %1}, %2;" : "=f"(r.x), "=f"(r.y) : "l"(v));
    return r;
}

// ---------------- 64x64 GEMM mainloop, 4x4 microtile, f32x2 accum -------------
// Double-buffered register prefetch hides L2 latency; A stored into smem
// pre-duplicated so the inner loop needs no operand-packing MOVs.
// acc[i][0..1] hold cols tx*4 .. tx*4+3 for row ty*4+i.
__device__ __forceinline__ void gemm_main(
    const float* __restrict__ A, int lda, int M,
    const float* __restrict__ B, int ldb,
    int row0, int col0, int kstart, int klen, float* sm,
    unsigned long long (&acc)[4][2])
{
    float (*As2)[140] = (float(*)[140])sm;             // [16][140] dup'd A
    float (*Bs)[68]   = (float(*)[68])(sm + 16 * 140); // [16][68] padded

    int tid = threadIdx.x;
    int tx = tid & 15, ty = tid >> 4;

    #pragma unroll
    for (int i = 0; i < 4; i++) {
        acc[i][0] = 0ull; acc[i][1] = 0ull;
    }

    int ar = tid >> 2, ak = (tid & 3) * 4;           // A loader: 64 rows x 16 k
    bool avalid = (row0 + ar) < M;
    const float* Arow = A + (row0 + ar) * lda + kstart + ak;
    int brow = tid >> 4, bcol = (tid & 15) * 4;      // B loader: 16 k x 64 n
    const float* Brow = B + (kstart + brow) * ldb + col0 + bcol;

    // prefetch iter 0
    float4 av = make_float4(0.f, 0.f, 0.f, 0.f);
    if (avalid) av = *(const float4*)Arow;
    float4 bv = *(const float4*)Brow;

    for (int k0 = 0; k0 < klen; k0 += 16) {
        // store current iter to smem (A duplicated pairwise)
        *(float2*)&As2[ak + 0][ar * 2] = make_float2(av.x, av.x);
        *(float2*)&As2[ak + 1][ar * 2] = make_float2(av.y, av.y);
        *(float2*)&As2[ak + 2][ar * 2] = make_float2(av.z, av.z);
        *(float2*)&As2[ak + 3][ar * 2] = make_float2(av.w, av.w);
        *(float4*)&Bs[brow][bcol] = bv;
        __syncthreads();

        // prefetch next iter (overlaps with compute below)
        if (k0 + 16 < klen) {
            av = make_float4(0.f, 0.f, 0.f, 0.f);
            if (avalid) av = *(const float4*)(Arow + k0 + 16);
            bv = *(const float4*)(Brow + (k0 + 16) * ldb);
        }

        #pragma unroll
        for (int k = 0; k < 16; k++) {
            ulonglong2 aa01 = *(ulonglong2*)&As2[k][ty * 8];
            ulonglong2 aa23 = *(ulonglong2*)&As2[k][ty * 8 + 4];
            ulonglong2 b    = *(ulonglong2*)&Bs[k][tx * 4];
            ffma2(acc[0][0], aa01.x, b.x); ffma2(acc[0][1], aa01.x, b.y);
            ffma2(acc[1][0], aa01.y, b.x); ffma2(acc[1][1], aa01.y, b.y);
            ffma2(acc[2][0], aa23.x, b.x); ffma2(acc[2][1], aa23.x, b.y);
            ffma2(acc[3][0], aa23.y, b.x); ffma2(acc[3][1], aa23.y, b.y);
        }
        __syncthreads();
    }
}

// unpack one acc row into 4 floats
__device__ __forceinline__ void unpack_row(unsigned long long (&acc)[4][2],
                                           int i, float* v)
{
    float2 v0 = up2(acc[i][0]), v1 = up2(acc[i][1]);
    v[0] = v0.x; v[1] = v0.y; v[2] = v1.x; v[3] = v1.y;
}

// ---------------- block LayerNorm over 256-elem row (256 threads) -------------
__device__ __forceinline__ float ln_norm(float v, float w, float b, float* red)
{
    int tid = threadIdx.x;
    float t = v;
    #pragma unroll
    for (int off = 16; off; off >>= 1) t += __shfl_xor_sync(0xffffffffu, t, off);
    __syncthreads();
    if ((tid & 31) == 0) red[tid >> 5] = t;
    __syncthreads();
    float mean = (red[0] + red[1] + red[2] + red[3] +
                  red[4] + red[5] + red[6] + red[7]) * (1.0f / EMBD);
    float d = v - mean;
    t = d * d;
    #pragma unroll
    for (int off = 16; off; off >>= 1) t += __shfl_xor_sync(0xffffffffu, t, off);
    __syncthreads();
    if ((tid & 31) == 0) red[tid >> 5] = t;
    __syncthreads();
    float var = (red[0] + red[1] + red[2] + red[3] +
                 red[4] + red[5] + red[6] + red[7]) * (1.0f / EMBD);
    return d * rsqrtf(var + 1e-5f) * w + b;
}

// ---------------- attention smem layout (floats) ----------------
#define A_KS 0
#define A_VS (32 * 200)
#define A_SS (A_VS + NTOK * DHD)
#define A_QS (A_SS + 32 * 200)
#define A_IV (A_QS + 32 * 32)
#define SMEM_FLOATS (A_IV + 32)
#define SMEM_BYTES  (SMEM_FLOATS * 4)

__device__ void attn_tile(int qt, int h, int s, float* buf)
{
    float (*Ks)[200] = (float(*)[200])(buf + A_KS);
    float (*Vs)[DHD] = (float(*)[DHD])(buf + A_VS);
    float (*Ss)[200] = (float(*)[200])(buf + A_SS);
    float (*Qs)[DHD] = (float(*)[DHD])(buf + A_QS);
    float* inv = buf + A_IV;
    int tid = threadIdx.x;

    const float* gk = g_k[1 - s][h];
    const float* gv = g_v[1 - s][h];
    const float* gq = g_q[s][h];

    for (int i = tid; i < 32 * 50; i += NTHR)
        ((float4*)(buf + A_KS))[i] = ((const float4*)gk)[i];
    for (int i = tid; i < NTOK * 8; i += NTHR)
        ((float4*)(buf + A_VS))[i] = ((const float4*)gv)[i];
    for (int i = tid; i < 32 * 8; i += NTHR) {
        int q = i >> 3, d4 = (i & 7) << 2;
        int qg = qt * 32 + q;
        float4 v = make_float4(0.f, 0.f, 0.f, 0.f);
        if (qg < NTOK) v = *(const float4*)&gq[qg * DHD + d4];
        *(float4*)&Qs[q][d4] = v;
    }
    __syncthreads();

    // scores
    {
        int q = tid >> 3, g = tid & 7;
        float qr[32];
        #pragma unroll
        for (int d = 0; d < 32; d++) qr[d] = Qs[q][d];
        #pragma unroll
        for (int kk = 0; kk < 7; kk++) {
            int j0 = g * 4 + kk * 32;
            if (j0 >= NTOK) break;
            float a0 = 0.f, a1 = 0.f, a2 = 0.f, a3 = 0.f;
            #pragma unroll
            for (int d = 0; d < 32; d++) {
                float4 kv = *(float4*)&Ks[d][j0];
                a0 += qr[d] * kv.x; a1 += qr[d] * kv.y;
                a2 += qr[d] * kv.z; a3 += qr[d] * kv.w;
            }
            Ss[q][j0 + 0] = a0 * 0.0625f;
            Ss[q][j0 + 1] = a1 * 0.0625f;
            Ss[q][j0 + 2] = a2 * 0.0625f;
            Ss[q][j0 + 3] = a3 * 0.0625f;
        }
    }
    __syncthreads();

    // softmax
    {
        int w = tid >> 5, lane = tid & 31;
        for (int r = 0; r < 4; r++) {
            int q = w * 4 + r;
            float m = -1e30f;
            for (int j = lane; j < NTOK; j += 32) m = fmaxf(m, Ss[q][j]);
            #pragma unroll
            for (int off = 16; off; off >>= 1)
                m = fmaxf(m, __shfl_xor_sync(0xffffffffu, m, off));
            float sum = 0.f;
            for (int j = lane; j < NTOK; j += 32) {
                float e = __expf(Ss[q][j] - m);
                Ss[q][j] = e;
                sum += e;
            }
            #pragma unroll
            for (int off = 16; off; off >>= 1)
                sum += __shfl_xor_sync(0xffffffffu, sum, off);
            if (lane == 0) inv[q] = 1.0f / sum;
        }
    }
    __syncthreads();

    // PV
    {
        int q = tid >> 3, d0 = (tid & 7) * 4;
        float4 acc = make_float4(0.f, 0.f, 0.f, 0.f);
        for (int j = 0; j < NTOK; j += 2) {
            float p0 = Ss[q][j], p1 = Ss[q][j + 1];
            float4 v0 = *(float4*)&Vs[j][d0];
            float4 v1 = *(float4*)&Vs[j + 1][d0];
            acc.x += p0 * v0.x + p1 * v1.x;
            acc.y += p0 * v0.y + p1 * v1.y;
            acc.z += p0 * v0.z + p1 * v1.z;
            acc.w += p0 * v0.w + p1 * v1.w;
        }
        float iv = inv[q];
        acc.x *= iv; acc.y *= iv; acc.z *= iv; acc.w *= iv;
        int qg = qt * 32 + q;
        if (qg < NTOK)
            *(float4*)&g_attn[s][qg * EMBD + h * DHD + d0] = acc;
    }
}

// ---------------- fused persistent kernel ----------------
struct Params {
    const float *vis, *ir;
    const float *ln1w[2], *ln1b[2], *ln2w[2], *ln2b[2];
    const float *Wqkv[2], *bqkv[2], *Wp[2], *bp[2];
    const float *W1[2], *b1[2], *W2[2], *b2[2];
    float* out;
};

__global__ void __launch_bounds__(NTHR, 2) fused(Params p)
{
    extern __shared__ float sm[];
    int b = blockIdx.x;
    int tid = threadIdx.x;
    int tx = tid & 15, ty = tid >> 4;
    unsigned long long acc[4][2];

    // ---- S0: QKV GEMM K=256 (96 items, 64x64) w/ fused bias + deinterleave,
    //          LN1 on the remaining 200 blocks ----
    if (b < 96) {
        int t = b;
        int nt = t % 12; t /= 12;
        int mt = t % 4; t /= 4;
        int s = t;
        int row0 = mt * 64, col0 = nt * 64;
        gemm_main(s ? p.ir : p.vis, EMBD, NTOK, p.Wqkv[s], 768,
                  row0, col0, 0, 256, sm, acc);
        const float* bq = p.bqkv[s];
        #pragma unroll
        for (int i = 0; i < 4; i++) {
            int n = row0 + ty * 4 + i;
            if (n < NTOK) {
                float v[4];
                unpack_row(acc, i, v);
                #pragma unroll
                for (int j = 0; j < 4; j++) {
                    int c = col0 + tx * 4 + j;
                    float val = v[j] + bq[c];
                    int hd = c / 3, t3 = c - hd * 3;
                    int h = hd >> 5, d = hd & 31;
                    if (t3 == 0)      g_q[s][h][n * DHD + d] = val;
                    else if (t3 == 1) g_k[s][h][d * 200 + n] = val;
                    else              g_v[s][h][n * DHD + d] = val;
                }
            }
        }
    } else {
        for (int r = b - 96; r < 2 * NTOK; r += NB - 96) {
            int s = r >= NTOK;
            int n = s ? r - NTOK : r;
            float v = (s ? p.ir : p.vis)[n * EMBD + tid];
            g_nrm1[s][n * EMBD + tid] =
                ln_norm(v, p.ln1w[s][tid], p.ln1b[s][tid], sm);
        }
    }
    gsync();

    // ---- S1: cross attention (112 items) ----
    if (b < 112) {
        int t = b;
        int qt = t % 7; t /= 7;
        int h = t % 8;
        int s = t / 8;
        attn_tile(qt, h, s, sm);
    }
    gsync();

    // ---- S2: proj split-K=4 partial GEMMs (128 items, 64x64, K=64) ----
    if (b < 128) {
        int t = b;
        int nt = t & 3; t >>= 2;
        int mt = t & 3; t >>= 2;
        int s = t & 1, ks = t >> 1;
        int row0 = mt * 64, col0 = nt * 64;
        gemm_main(g_attn[s], EMBD, NTOK, p.Wp[s], EMBD,
                  row0, col0, ks * 64, 64, sm, acc);
        float* Cp = g_part[ks * 2 + s];
        #pragma unroll
        for (int i = 0; i < 4; i++) {
            int r = row0 + ty * 4 + i;
            if (r < NTOK) {
                float v[4];
                unpack_row(acc, i, v);
                *(float4*)&Cp[r * EMBD + col0 + tx * 4] = *(float4*)&v[0];
            }
        }
    }
    gsync();

    // ---- S3: proj reduce + bias + residual + LN2 ----
    for (int r = b; r < 2 * NTOK; r += NB) {
        int s = r >= NTOK;
        int n = s ? r - NTOK : r;
        int idx = n * EMBD + tid;
        float v = g_part[s][idx] + g_part[2 + s][idx] +
                  g_part[4 + s][idx] + g_part[6 + s][idx] +
                  p.bp[s][tid] + g_nrm1[s][idx];
        g_l[s][idx] = ln_norm(v, p.ln2w[s][tid], p.ln2b[s][tid], sm);
    }
    gsync();

    // ---- S4: FF1 GEMM K=256 (128 items, 64x64) w/ fused bias + exact GELU ----
    if (b < 128) {
        int t = b;
        int nt = t & 15; t >>= 4;
        int mt = t & 3; t >>= 2;
        int s = t;
        int row0 = mt * 64, col0 = nt * 64;
        gemm_main(g_l[s], EMBD, NTOK, p.W1[s], HIDD,
                  row0, col0, 0, 256, sm, acc);
        const float* b1 = p.b1[s];
        #pragma unroll
        for (int i = 0; i < 4; i++) {
            int r = row0 + ty * 4 + i;
            if (r < NTOK) {
                float v[4];
                unpack_row(acc, i, v);
                #pragma unroll
                for (int j = 0; j < 4; j++) {
                    float x = v[j] + b1[col0 + tx * 4 + j];
                    v[j] = 0.5f * x * (1.0f + erff(x * 0.70710678118654752f));
                }
                *(float4*)&g_hid[s][r * HIDD + col0 + tx * 4] = *(float4*)&v[0];
            }
        }
    }
    gsync();

    // ---- S5: FF2 split-K=8 partial GEMMs (256 items, 64x64, K=128) ----
    if (b < 256) {
        int t = b;
        int nt = t & 3; t >>= 2;
        int mt = t & 3; t >>= 2;
        int s = t & 1, ks = t >> 1;      // ks 0..7
        int row0 = mt * 64, col0 = nt * 64;
        gemm_main(g_hid[s], HIDD, NTOK, p.W2[s], EMBD,
                  row0, col0, ks * 128, 128, sm, acc);
        float* Cp = g_part[ks * 2 + s];
        #pragma unroll
        for (int i = 0; i < 4; i++) {
            int r = row0 + ty * 4 + i;
            if (r < NTOK) {
                float v[4];
                unpack_row(acc, i, v);
                *(float4*)&Cp[r * EMBD + col0 + tx * 4] = *(float4*)&v[0];
            }
        }
    }
    gsync();

    // ---- S6: FF2 reduce + bias + residual + pixel-shuffle to d_out ----
    for (int r = b; r < 2 * NTOK; r += NB) {
        int s = r >= NTOK;
        int n = s ? r - NTOK : r;
        int idx = n * EMBD + tid;
        float v = 0.f;
        #pragma unroll
        for (int ks = 0; ks < 8; ks++) v += g_part[ks * 2 + s][idx];
        v += p.b2[s][tid] + g_l[s][idx];
        int i = n / 14, j = n % 14;
        int pp = tid >> 4, q = tid & 15;
        int ch = s ? 0 : 1;
        p.out[ch * 50176 + pp * 3136 + q * 196 + i * 14 + j] = v;
    }
}

// ---------------- launch ----------------
extern "C" void kernel_launch(void* const* d_in, const int* in_sizes, int n_in,
                              void* d_out, int out_size)
{
    Params pr;
    pr.vis = (const float*)d_in[0];
    pr.ir  = (const float*)d_in[1];
    pr.ln1w[0] = (const float*)d_in[2];  pr.ln1b[0] = (const float*)d_in[3];
    pr.ln1w[1] = (const float*)d_in[4];  pr.ln1b[1] = (const float*)d_in[5];
    pr.ln2w[0] = (const float*)d_in[6];  pr.ln2b[0] = (const float*)d_in[7];
    pr.ln2w[1] = (const float*)d_in[8];  pr.ln2b[1] = (const float*)d_in[9];
    pr.Wqkv[0] = (const float*)d_in[10]; pr.bqkv[0] = (const float*)d_in[11];
    pr.Wqkv[1] = (const float*)d_in[12]; pr.bqkv[1] = (const float*)d_in[13];
    pr.Wp[0]   = (const float*)d_in[14]; pr.bp[0]   = (const float*)d_in[15];
    pr.Wp[1]   = (const float*)d_in[16]; pr.bp[1]   = (const float*)d_in[17];
    pr.W1[0]   = (const float*)d_in[18]; pr.b1[0]   = (const float*)d_in[19];
    pr.W2[0]   = (const float*)d_in[20]; pr.b2[0]   = (const float*)d_in[21];
    pr.W1[1]   = (const float*)d_in[22]; pr.b1[1]   = (const float*)d_in[23];
    pr.W2[1]   = (const float*)d_in[24]; pr.b2[1]   = (const float*)d_in[25];
    pr.out = (float*)d_out;

    cudaFuncSetAttribute(fused, cudaFuncAttributeMaxDynamicSharedMemorySize,
                         SMEM_BYTES);
    fused<<<NB, NTHR, SMEM_BYTES>>>(pr);
}

// round 11
// speedup vs baseline: 2.6457x; 1.0498x over previous
#include <cuda_runtime.h>
#include <math.h>

#define NTOK 196
#define EMBD 256
#define HIDD 1024
#define NH   8
#define DHD  32
#define NB   296
#define NTHR 256

// ---------------- scratch (allocation-free: __device__ globals) ----------------
__device__ float g_part[16][NTOK * EMBD]; // split-K partials (proj / FF2)
__device__ float g_nrm1[2][NTOK * EMBD];  // LN1 outputs (residual base)
__device__ float g_q[2][NH][NTOK * DHD];  // deinterleaved Q  [n][d]
__device__ float g_k[2][NH][DHD * 200];   // deinterleaved K  [d][n] (pad 200)
__device__ float g_v[2][NH][NTOK * DHD];  // deinterleaved V  [n][d]
__device__ float g_attn[2][NTOK * EMBD];  // attention output
__device__ float g_l[2][NTOK * EMBD];     // LN2 outputs
__device__ float g_hid[2][NTOK * HIDD];   // FF hidden (post-GELU)
__device__ unsigned g_count = 0;
__device__ unsigned g_gen = 0;

// ---------------- grid-wide barrier (all NB blocks co-resident) ----------------
__device__ __forceinline__ void gsync()
{
    __syncthreads();
    if (threadIdx.x == 0) {
        __threadfence();
        unsigned gen = *(volatile unsigned*)&g_gen;
        if (atomicAdd(&g_count, 1u) == NB - 1u) {
            g_count = 0u;
            __threadfence();
            atomicAdd(&g_gen, 1u);
        } else {
            while (*(volatile unsigned*)&g_gen == gen) { }
        }
        __threadfence();
    }
    __syncthreads();
}

// ---------------- packed fp32x2 FMA helpers ----------------
__device__ __forceinline__ void ffma2(unsigned long long& acc,
                                      unsigned long long a, unsigned long long b)
{
    asm("fma.rn.f32x2 %0, %1, %2, %0;" : "+l"(acc) : "l"(a), "l"(b));
}
__device__ __forceinline__ float2 up2(unsigned long long v)
{
    float2 r;
    asm("mov.b64 {%0, %1}, %2;" : "=f"(r.x), "=f"(r.y) : "l"(v));
    return r;
}

// warp-remapped microtile coordinates: 4x8 lanes per warp
__device__ __forceinline__ int mt_ty(int tid)
{
    return (((tid >> 5) & 3) << 2) + ((tid & 31) >> 3);
}
__device__ __forceinline__ int mt_tx(int tid)
{
    return (((tid >> 5) >> 2) << 3) + (tid & 7);
}

// ---------------- 64x64 GEMM mainloop, 4x4 microtile, f32x2 accum -------------
// Double-buffered smem (1 sync per 32-k slab), register prefetch, A stored
// pre-duplicated (no operand-packing MOVs in inner loop).
// Buffer layout (floats): As2[32][140] then Bs[32][68]; two buffers.
#define GBUF (32 * 140 + 32 * 68)

__device__ __forceinline__ void gemm_main(
    const float* __restrict__ A, int lda, int M,
    const float* __restrict__ B, int ldb,
    int row0, int col0, int kstart, int klen, float* sm,
    unsigned long long (&acc)[4][2])
{
    int tid = threadIdx.x;
    int tx = mt_tx(tid), ty = mt_ty(tid);

    #pragma unroll
    for (int i = 0; i < 4; i++) {
        acc[i][0] = 0ull; acc[i][1] = 0ull;
    }

    int ar = tid >> 2, ak = (tid & 3) * 4;           // A loader: 64 rows, k ak / ak+16
    bool avalid = (row0 + ar) < M;
    const float* Arow = A + (row0 + ar) * lda + kstart + ak;
    int brow = tid >> 4, bcol = (tid & 15) * 4;      // B loader: k brow / brow+16
    const float* Brow = B + (kstart + brow) * ldb + col0 + bcol;

    // prefetch slab 0
    float4 av0 = make_float4(0.f, 0.f, 0.f, 0.f), av1 = av0;
    if (avalid) {
        av0 = *(const float4*)Arow;
        av1 = *(const float4*)(Arow + 16);
    }
    float4 bv0 = *(const float4*)Brow;
    float4 bv1 = *(const float4*)(Brow + 16 * ldb);

    int nbuf = 0;
    for (int k0 = 0; k0 < klen; k0 += 32) {
        float* base = sm + nbuf * GBUF;
        float (*As2)[140] = (float(*)[140])base;
        float (*Bs)[68]   = (float(*)[68])(base + 32 * 140);

        // store current slab (A duplicated pairwise)
        *(float2*)&As2[ak + 0][ar * 2]  = make_float2(av0.x, av0.x);
        *(float2*)&As2[ak + 1][ar * 2]  = make_float2(av0.y, av0.y);
        *(float2*)&As2[ak + 2][ar * 2]  = make_float2(av0.z, av0.z);
        *(float2*)&As2[ak + 3][ar * 2]  = make_float2(av0.w, av0.w);
        *(float2*)&As2[ak + 16][ar * 2] = make_float2(av1.x, av1.x);
        *(float2*)&As2[ak + 17][ar * 2] = make_float2(av1.y, av1.y);
        *(float2*)&As2[ak + 18][ar * 2] = make_float2(av1.z, av1.z);
        *(float2*)&As2[ak + 19][ar * 2] = make_float2(av1.w, av1.w);
        *(float4*)&Bs[brow][bcol]      = bv0;
        *(float4*)&Bs[brow + 16][bcol] = bv1;
        __syncthreads();

        // prefetch next slab (overlaps compute)
        if (k0 + 32 < klen) {
            if (avalid) {
                av0 = *(const float4*)(Arow + k0 + 32);
                av1 = *(const float4*)(Arow + k0 + 48);
            }
            bv0 = *(const float4*)(Brow + (k0 + 32) * ldb);
            bv1 = *(const float4*)(Brow + (k0 + 48) * ldb);
        }

        #pragma unroll
        for (int k = 0; k < 32; k++) {
            ulonglong2 aa01 = *(ulonglong2*)&As2[k][ty * 8];
            ulonglong2 aa23 = *(ulonglong2*)&As2[k][ty * 8 + 4];
            ulonglong2 b    = *(ulonglong2*)&Bs[k][tx * 4];
            ffma2(acc[0][0], aa01.x, b.x); ffma2(acc[0][1], aa01.x, b.y);
            ffma2(acc[1][0], aa01.y, b.x); ffma2(acc[1][1], aa01.y, b.y);
            ffma2(acc[2][0], aa23.x, b.x); ffma2(acc[2][1], aa23.x, b.y);
            ffma2(acc[3][0], aa23.y, b.x); ffma2(acc[3][1], aa23.y, b.y);
        }
        nbuf ^= 1;
    }
}

// unpack one acc row into 4 floats
__device__ __forceinline__ void unpack_row(unsigned long long (&acc)[4][2],
                                           int i, float* v)
{
    float2 v0 = up2(acc[i][0]), v1 = up2(acc[i][1]);
    v[0] = v0.x; v[1] = v0.y; v[2] = v1.x; v[3] = v1.y;
}

// ---------------- block LayerNorm over 256-elem row (256 threads) -------------
__device__ __forceinline__ float ln_norm(float v, float w, float b, float* red)
{
    int tid = threadIdx.x;
    float t = v;
    #pragma unroll
    for (int off = 16; off; off >>= 1) t += __shfl_xor_sync(0xffffffffu, t, off);
    __syncthreads();
    if ((tid & 31) == 0) red[tid >> 5] = t;
    __syncthreads();
    float mean = (red[0] + red[1] + red[2] + red[3] +
                  red[4] + red[5] + red[6] + red[7]) * (1.0f / EMBD);
    float d = v - mean;
    t = d * d;
    #pragma unroll
    for (int off = 16; off; off >>= 1) t += __shfl_xor_sync(0xffffffffu, t, off);
    __syncthreads();
    if ((tid & 31) == 0) red[tid >> 5] = t;
    __syncthreads();
    float var = (red[0] + red[1] + red[2] + red[3] +
                 red[4] + red[5] + red[6] + red[7]) * (1.0f / EMBD);
    return d * rsqrtf(var + 1e-5f) * w + b;
}

// ---------------- attention smem layout (floats) ----------------
#define A_KS 0
#define A_VS (32 * 200)
#define A_SS (A_VS + NTOK * DHD)
#define A_QS (A_SS + 32 * 200)
#define A_IV (A_QS + 32 * 32)
#define SMEM_FLOATS (A_IV + 32)
#define SMEM_BYTES  (SMEM_FLOATS * 4)

__device__ void attn_tile(int qt, int h, int s, float* buf)
{
    float (*Ks)[200] = (float(*)[200])(buf + A_KS);
    float (*Vs)[DHD] = (float(*)[DHD])(buf + A_VS);
    float (*Ss)[200] = (float(*)[200])(buf + A_SS);
    float (*Qs)[DHD] = (float(*)[DHD])(buf + A_QS);
    float* inv = buf + A_IV;
    int tid = threadIdx.x;

    const float* gk = g_k[1 - s][h];
    const float* gv = g_v[1 - s][h];
    const float* gq = g_q[s][h];

    for (int i = tid; i < 32 * 50; i += NTHR)
        ((float4*)(buf + A_KS))[i] = ((const float4*)gk)[i];
    for (int i = tid; i < NTOK * 8; i += NTHR)
        ((float4*)(buf + A_VS))[i] = ((const float4*)gv)[i];
    for (int i = tid; i < 32 * 8; i += NTHR) {
        int q = i >> 3, d4 = (i & 7) << 2;
        int qg = qt * 32 + q;
        float4 v = make_float4(0.f, 0.f, 0.f, 0.f);
        if (qg < NTOK) v = *(const float4*)&gq[qg * DHD + d4];
        *(float4*)&Qs[q][d4] = v;
    }
    __syncthreads();

    // scores
    {
        int q = tid >> 3, g = tid & 7;
        float qr[32];
        #pragma unroll
        for (int d = 0; d < 32; d++) qr[d] = Qs[q][d];
        #pragma unroll
        for (int kk = 0; kk < 7; kk++) {
            int j0 = g * 4 + kk * 32;
            if (j0 >= NTOK) break;
            float a0 = 0.f, a1 = 0.f, a2 = 0.f, a3 = 0.f;
            #pragma unroll
            for (int d = 0; d < 32; d++) {
                float4 kv = *(float4*)&Ks[d][j0];
                a0 += qr[d] * kv.x; a1 += qr[d] * kv.y;
                a2 += qr[d] * kv.z; a3 += qr[d] * kv.w;
            }
            Ss[q][j0 + 0] = a0 * 0.0625f;
            Ss[q][j0 + 1] = a1 * 0.0625f;
            Ss[q][j0 + 2] = a2 * 0.0625f;
            Ss[q][j0 + 3] = a3 * 0.0625f;
        }
    }
    __syncthreads();

    // softmax
    {
        int w = tid >> 5, lane = tid & 31;
        for (int r = 0; r < 4; r++) {
            int q = w * 4 + r;
            float m = -1e30f;
            for (int j = lane; j < NTOK; j += 32) m = fmaxf(m, Ss[q][j]);
            #pragma unroll
            for (int off = 16; off; off >>= 1)
                m = fmaxf(m, __shfl_xor_sync(0xffffffffu, m, off));
            float sum = 0.f;
            for (int j = lane; j < NTOK; j += 32) {
                float e = __expf(Ss[q][j] - m);
                Ss[q][j] = e;
                sum += e;
            }
            #pragma unroll
            for (int off = 16; off; off >>= 1)
                sum += __shfl_xor_sync(0xffffffffu, sum, off);
            if (lane == 0) inv[q] = 1.0f / sum;
        }
    }
    __syncthreads();

    // PV
    {
        int q = tid >> 3, d0 = (tid & 7) * 4;
        float4 acc = make_float4(0.f, 0.f, 0.f, 0.f);
        for (int j = 0; j < NTOK; j += 2) {
            float p0 = Ss[q][j], p1 = Ss[q][j + 1];
            float4 v0 = *(float4*)&Vs[j][d0];
            float4 v1 = *(float4*)&Vs[j + 1][d0];
            acc.x += p0 * v0.x + p1 * v1.x;
            acc.y += p0 * v0.y + p1 * v1.y;
            acc.z += p0 * v0.z + p1 * v1.z;
            acc.w += p0 * v0.w + p1 * v1.w;
        }
        float iv = inv[q];
        acc.x *= iv; acc.y *= iv; acc.z *= iv; acc.w *= iv;
        int qg = qt * 32 + q;
        if (qg < NTOK)
            *(float4*)&g_attn[s][qg * EMBD + h * DHD + d0] = acc;
    }
}

// ---------------- fused persistent kernel ----------------
struct Params {
    const float *vis, *ir;
    const float *ln1w[2], *ln1b[2], *ln2w[2], *ln2b[2];
    const float *Wqkv[2], *bqkv[2], *Wp[2], *bp[2];
    const float *W1[2], *b1[2], *W2[2], *b2[2];
    float* out;
};

__global__ void __launch_bounds__(NTHR, 2) fused(Params p)
{
    extern __shared__ float sm[];
    int b = blockIdx.x;
    int tid = threadIdx.x;
    int tx = mt_tx(tid), ty = mt_ty(tid);
    unsigned long long acc[4][2];

    // ---- S0: QKV GEMM K=256 (96 items, 64x64) w/ fused bias + deinterleave,
    //          LN1 on the remaining 200 blocks ----
    if (b < 96) {
        int t = b;
        int nt = t % 12; t /= 12;
        int mt = t % 4; t /= 4;
        int s = t;
        int row0 = mt * 64, col0 = nt * 64;
        gemm_main(s ? p.ir : p.vis, EMBD, NTOK, p.Wqkv[s], 768,
                  row0, col0, 0, 256, sm, acc);
        const float* bq = p.bqkv[s];
        #pragma unroll
        for (int i = 0; i < 4; i++) {
            int n = row0 + ty * 4 + i;
            if (n < NTOK) {
                float v[4];
                unpack_row(acc, i, v);
                #pragma unroll
                for (int j = 0; j < 4; j++) {
                    int c = col0 + tx * 4 + j;
                    float val = v[j] + bq[c];
                    int hd = c / 3, t3 = c - hd * 3;
                    int h = hd >> 5, d = hd & 31;
                    if (t3 == 0)      g_q[s][h][n * DHD + d] = val;
                    else if (t3 == 1) g_k[s][h][d * 200 + n] = val;
                    else              g_v[s][h][n * DHD + d] = val;
                }
            }
        }
    } else {
        for (int r = b - 96; r < 2 * NTOK; r += NB - 96) {
            int s = r >= NTOK;
            int n = s ? r - NTOK : r;
            float v = (s ? p.ir : p.vis)[n * EMBD + tid];
            g_nrm1[s][n * EMBD + tid] =
                ln_norm(v, p.ln1w[s][tid], p.ln1b[s][tid], sm);
        }
    }
    gsync();

    // ---- S1: cross attention (112 items) ----
    if (b < 112) {
        int t = b;
        int qt = t % 7; t /= 7;
        int h = t % 8;
        int s = t / 8;
        attn_tile(qt, h, s, sm);
    }
    gsync();

    // ---- S2: proj split-K=4 partial GEMMs (128 items, 64x64, K=64) ----
    if (b < 128) {
        int t = b;
        int nt = t & 3; t >>= 2;
        int mt = t & 3; t >>= 2;
        int s = t & 1, ks = t >> 1;
        int row0 = mt * 64, col0 = nt * 64;
        gemm_main(g_attn[s], EMBD, NTOK, p.Wp[s], EMBD,
                  row0, col0, ks * 64, 64, sm, acc);
        float* Cp = g_part[ks * 2 + s];
        #pragma unroll
        for (int i = 0; i < 4; i++) {
            int r = row0 + ty * 4 + i;
            if (r < NTOK) {
                float v[4];
                unpack_row(acc, i, v);
                *(float4*)&Cp[r * EMBD + col0 + tx * 4] = *(float4*)&v[0];
            }
        }
    }
    gsync();

    // ---- S3: proj reduce + bias + residual + LN2 ----
    for (int r = b; r < 2 * NTOK; r += NB) {
        int s = r >= NTOK;
        int n = s ? r - NTOK : r;
        int idx = n * EMBD + tid;
        float v = g_part[s][idx] + g_part[2 + s][idx] +
                  g_part[4 + s][idx] + g_part[6 + s][idx] +
                  p.bp[s][tid] + g_nrm1[s][idx];
        g_l[s][idx] = ln_norm(v, p.ln2w[s][tid], p.ln2b[s][tid], sm);
    }
    gsync();

    // ---- S4: FF1 GEMM K=256 (128 items, 64x64) w/ fused bias + exact GELU ----
    if (b < 128) {
        int t = b;
        int nt = t & 15; t >>= 4;
        int mt = t & 3; t >>= 2;
        int s = t;
        int row0 = mt * 64, col0 = nt * 64;
        gemm_main(g_l[s], EMBD, NTOK, p.W1[s], HIDD,
                  row0, col0, 0, 256, sm, acc);
        const float* b1 = p.b1[s];
        #pragma unroll
        for (int i = 0; i < 4; i++) {
            int r = row0 + ty * 4 + i;
            if (r < NTOK) {
                float v[4];
                unpack_row(acc, i, v);
                #pragma unroll
                for (int j = 0; j < 4; j++) {
                    float x = v[j] + b1[col0 + tx * 4 + j];
                    v[j] = 0.5f * x * (1.0f + erff(x * 0.70710678118654752f));
                }
                *(float4*)&g_hid[s][r * HIDD + col0 + tx * 4] = *(float4*)&v[0];
            }
        }
    }
    gsync();

    // ---- S5: FF2 split-K=8 partial GEMMs (256 items, 64x64, K=128) ----
    if (b < 256) {
        int t = b;
        int nt = t & 3; t >>= 2;
        int mt = t & 3; t >>= 2;
        int s = t & 1, ks = t >> 1;      // ks 0..7
        int row0 = mt * 64, col0 = nt * 64;
        gemm_main(g_hid[s], HIDD, NTOK, p.W2[s], EMBD,
                  row0, col0, ks * 128, 128, sm, acc);
        float* Cp = g_part[ks * 2 + s];
        #pragma unroll
        for (int i = 0; i < 4; i++) {
            int r = row0 + ty * 4 + i;
            if (r < NTOK) {
                float v[4];
                unpack_row(acc, i, v);
                *(float4*)&Cp[r * EMBD + col0 + tx * 4] = *(float4*)&v[0];
            }
        }
    }
    gsync();

    // ---- S6: FF2 reduce + bias + residual + pixel-shuffle to d_out ----
    for (int r = b; r < 2 * NTOK; r += NB) {
        int s = r >= NTOK;
        int n = s ? r - NTOK : r;
        int idx = n * EMBD + tid;
        float v = 0.f;
        #pragma unroll
        for (int ks = 0; ks < 8; ks++) v += g_part[ks * 2 + s][idx];
        v += p.b2[s][tid] + g_l[s][idx];
        int i = n / 14, j = n % 14;
        int pp = tid >> 4, q = tid & 15;
        int ch = s ? 0 : 1;
        p.out[ch * 50176 + pp * 3136 + q * 196 + i * 14 + j] = v;
    }
}

// ---------------- launch ----------------
extern "C" void kernel_launch(void* const* d_in, const int* in_sizes, int n_in,
                              void* d_out, int out_size)
{
    Params pr;
    pr.vis = (const float*)d_in[0];
    pr.ir  = (const float*)d_in[1];
    pr.ln1w[0] = (const float*)d_in[2];  pr.ln1b[0] = (const float*)d_in[3];
    pr.ln1w[1] = (const float*)d_in[4];  pr.ln1b[1] = (const float*)d_in[5];
    pr.ln2w[0] = (const float*)d_in[6];  pr.ln2b[0] = (const float*)d_in[7];
    pr.ln2w[1] = (const float*)d_in[8];  pr.ln2b[1] = (const float*)d_in[9];
    pr.Wqkv[0] = (const float*)d_in[10]; pr.bqkv[0] = (const float*)d_in[11];
    pr.Wqkv[1] = (const float*)d_in[12]; pr.bqkv[1] = (const float*)d_in[13];
    pr.Wp[0]   = (const float*)d_in[14]; pr.bp[0]   = (const float*)d_in[15];
    pr.Wp[1]   = (const float*)d_in[16]; pr.bp[1]   = (const float*)d_in[17];
    pr.W1[0]   = (const float*)d_in[18]; pr.b1[0]   = (const float*)d_in[19];
    pr.W2[0]   = (const float*)d_in[20]; pr.b2[0]   = (const float*)d_in[21];
    pr.W1[1]   = (const float*)d_in[22]; pr.b1[1]   = (const float*)d_in[23];
    pr.W2[1]   = (const float*)d_in[24]; pr.b2[1]   = (const float*)d_in[25];
    pr.out = (float*)d_out;

    cudaFuncSetAttribute(fused, cudaFuncAttributeMaxDynamicSharedMemorySize,
                         SMEM_BYTES);
    fused<<<NB, NTHR, SMEM_BYTES>>>(pr);
}

// round 12
// speedup vs baseline: 2.6979x; 1.0197x over previous
#include <cuda_runtime.h>
#include <math.h>

#define NTOK 196
#define EMBD 256
#define HIDD 1024
#define NH   8
#define DHD  32
#define NB   296
#define NTHR 256

// ---------------- scratch (allocation-free: __device__ globals) ----------------
__device__ float g_part[16][NTOK * EMBD]; // split-K partials (proj / FF2)
__device__ float g_nrm1[2][NTOK * EMBD];  // LN1 outputs (residual base)
__device__ float g_q[2][NH][NTOK * DHD];  // deinterleaved Q  [n][d]
__device__ float g_k[2][NH][DHD * 200];   // deinterleaved K  [d][n] (pad 200)
__device__ float g_v[2][NH][NTOK * DHD];  // deinterleaved V  [n][d]
__device__ float g_attn[2][NTOK * EMBD];  // attention output
__device__ float g_l[2][NTOK * EMBD];     // LN2 outputs
__device__ float g_hid[2][NTOK * HIDD];   // FF hidden (post-GELU)
__device__ unsigned g_count = 0;
__device__ unsigned g_gen = 0;

// ---------------- grid-wide barrier (all NB blocks co-resident) ----------------
__device__ __forceinline__ void gsync()
{
    __syncthreads();
    if (threadIdx.x == 0) {
        __threadfence();
        unsigned gen = *(volatile unsigned*)&g_gen;
        if (atomicAdd(&g_count, 1u) == NB - 1u) {
            g_count = 0u;
            __threadfence();
            atomicAdd(&g_gen, 1u);
        } else {
            while (*(volatile unsigned*)&g_gen == gen) { }
        }
        __threadfence();
    }
    __syncthreads();
}

// ---------------- packed fp32x2 FMA helpers ----------------
__device__ __forceinline__ void ffma2(unsigned long long& acc,
                                      unsigned long long a, unsigned long long b)
{
    asm("fma.rn.f32x2 %0, %1, %2, %0;" : "+l"(acc) : "l"(a), "l"(b));
}
__device__ __forceinline__ unsigned long long pk2(float x, float y)
{
    unsigned long long r;
    asm("mov.b64 %0, {%1, %2};" : "=l"(r) : "f"(x), "f"(y));
    return r;
}
__device__ __forceinline__ float2 up2(unsigned long long v)
{
    float2 r;
    asm("mov.b64 {%0, %1}, %2;" : "=f"(r.x), "=f"(r.y) : "l"(v));
    return r;
}

// warp-remapped microtile coordinates: 4x8 lanes per warp
__device__ __forceinline__ int mt_ty(int tid)
{
    return (((tid >> 5) & 3) << 2) + ((tid & 31) >> 3);
}
__device__ __forceinline__ int mt_tx(int tid)
{
    return (((tid >> 5) >> 2) << 3) + (tid & 7);
}

// ---------------- 64x64 GEMM mainloop, 4x4 microtile, f32x2 accum -------------
// Double-buffered smem (1 sync per 32-k slab), register prefetch, A stored
// pre-duplicated (no operand-packing MOVs in inner loop).
// Buffer layout (floats): As2[32][140] then Bs[32][68]; two buffers.
#define GBUF (32 * 140 + 32 * 68)

__device__ __forceinline__ void gemm_main(
    const float* __restrict__ A, int lda, int M,
    const float* __restrict__ B, int ldb,
    int row0, int col0, int kstart, int klen, float* sm,
    unsigned long long (&acc)[4][2])
{
    int tid = threadIdx.x;
    int tx = mt_tx(tid), ty = mt_ty(tid);

    #pragma unroll
    for (int i = 0; i < 4; i++) {
        acc[i][0] = 0ull; acc[i][1] = 0ull;
    }

    int ar = tid >> 2, ak = (tid & 3) * 4;           // A loader: 64 rows, k ak / ak+16
    bool avalid = (row0 + ar) < M;
    const float* Arow = A + (row0 + ar) * lda + kstart + ak;
    int brow = tid >> 4, bcol = (tid & 15) * 4;      // B loader: k brow / brow+16
    const float* Brow = B + (kstart + brow) * ldb + col0 + bcol;

    // prefetch slab 0
    float4 av0 = make_float4(0.f, 0.f, 0.f, 0.f), av1 = av0;
    if (avalid) {
        av0 = *(const float4*)Arow;
        av1 = *(const float4*)(Arow + 16);
    }
    float4 bv0 = *(const float4*)Brow;
    float4 bv1 = *(const float4*)(Brow + 16 * ldb);

    int nbuf = 0;
    for (int k0 = 0; k0 < klen; k0 += 32) {
        float* base = sm + nbuf * GBUF;
        float (*As2)[140] = (float(*)[140])base;
        float (*Bs)[68]   = (float(*)[68])(base + 32 * 140);

        // store current slab (A duplicated pairwise)
        *(float2*)&As2[ak + 0][ar * 2]  = make_float2(av0.x, av0.x);
        *(float2*)&As2[ak + 1][ar * 2]  = make_float2(av0.y, av0.y);
        *(float2*)&As2[ak + 2][ar * 2]  = make_float2(av0.z, av0.z);
        *(float2*)&As2[ak + 3][ar * 2]  = make_float2(av0.w, av0.w);
        *(float2*)&As2[ak + 16][ar * 2] = make_float2(av1.x, av1.x);
        *(float2*)&As2[ak + 17][ar * 2] = make_float2(av1.y, av1.y);
        *(float2*)&As2[ak + 18][ar * 2] = make_float2(av1.z, av1.z);
        *(float2*)&As2[ak + 19][ar * 2] = make_float2(av1.w, av1.w);
        *(float4*)&Bs[brow][bcol]      = bv0;
        *(float4*)&Bs[brow + 16][bcol] = bv1;
        __syncthreads();

        // prefetch next slab (overlaps compute)
        if (k0 + 32 < klen) {
            if (avalid) {
                av0 = *(const float4*)(Arow + k0 + 32);
                av1 = *(const float4*)(Arow + k0 + 48);
            }
            bv0 = *(const float4*)(Brow + (k0 + 32) * ldb);
            bv1 = *(const float4*)(Brow + (k0 + 48) * ldb);
        }

        #pragma unroll
        for (int k = 0; k < 32; k++) {
            ulonglong2 aa01 = *(ulonglong2*)&As2[k][ty * 8];
            ulonglong2 aa23 = *(ulonglong2*)&As2[k][ty * 8 + 4];
            ulonglong2 b    = *(ulonglong2*)&Bs[k][tx * 4];
            ffma2(acc[0][0], aa01.x, b.x); ffma2(acc[0][1], aa01.x, b.y);
            ffma2(acc[1][0], aa01.y, b.x); ffma2(acc[1][1], aa01.y, b.y);
            ffma2(acc[2][0], aa23.x, b.x); ffma2(acc[2][1], aa23.x, b.y);
            ffma2(acc[3][0], aa23.y, b.x); ffma2(acc[3][1], aa23.y, b.y);
        }
        nbuf ^= 1;
    }
}

// unpack one acc row into 4 floats
__device__ __forceinline__ void unpack_row(unsigned long long (&acc)[4][2],
                                           int i, float* v)
{
    float2 v0 = up2(acc[i][0]), v1 = up2(acc[i][1]);
    v[0] = v0.x; v[1] = v0.y; v[2] = v1.x; v[3] = v1.y;
}

// ---------------- block LayerNorm over 256-elem row (256 threads) -------------
__device__ __forceinline__ float ln_norm(float v, float w, float b, float* red)
{
    int tid = threadIdx.x;
    float t = v;
    #pragma unroll
    for (int off = 16; off; off >>= 1) t += __shfl_xor_sync(0xffffffffu, t, off);
    __syncthreads();
    if ((tid & 31) == 0) red[tid >> 5] = t;
    __syncthreads();
    float mean = (red[0] + red[1] + red[2] + red[3] +
                  red[4] + red[5] + red[6] + red[7]) * (1.0f / EMBD);
    float d = v - mean;
    t = d * d;
    #pragma unroll
    for (int off = 16; off; off >>= 1) t += __shfl_xor_sync(0xffffffffu, t, off);
    __syncthreads();
    if ((tid & 31) == 0) red[tid >> 5] = t;
    __syncthreads();
    float var = (red[0] + red[1] + red[2] + red[3] +
                 red[4] + red[5] + red[6] + red[7]) * (1.0f / EMBD);
    return d * rsqrtf(var + 1e-5f) * w + b;
}

// ---------------- attention smem layout (floats) ----------------
#define A_KS 0
#define A_VS (32 * 200)
#define A_SS (A_VS + NTOK * DHD)
#define A_QS (A_SS + 32 * 200)
#define A_IV (A_QS + 32 * 32)
#define SMEM_FLOATS (A_IV + 32)
#define SMEM_BYTES  (SMEM_FLOATS * 4)

__device__ void attn_tile(int qt, int h, int s, float* buf)
{
    float (*Ks)[200] = (float(*)[200])(buf + A_KS);
    float (*Vs)[DHD] = (float(*)[DHD])(buf + A_VS);
    float (*Ss)[200] = (float(*)[200])(buf + A_SS);
    float (*Qs)[DHD] = (float(*)[DHD])(buf + A_QS);
    float* inv = buf + A_IV;
    int tid = threadIdx.x;

    const float* gk = g_k[1 - s][h];
    const float* gv = g_v[1 - s][h];
    const float* gq = g_q[s][h];

    for (int i = tid; i < 32 * 50; i += NTHR)
        ((float4*)(buf + A_KS))[i] = ((const float4*)gk)[i];
    for (int i = tid; i < NTOK * 8; i += NTHR)
        ((float4*)(buf + A_VS))[i] = ((const float4*)gv)[i];
    for (int i = tid; i < 32 * 8; i += NTHR) {
        int q = i >> 3, d4 = (i & 7) << 2;
        int qg = qt * 32 + q;
        float4 v = make_float4(0.f, 0.f, 0.f, 0.f);
        if (qg < NTOK) v = *(const float4*)&gq[qg * DHD + d4];
        *(float4*)&Qs[q][d4] = v;
    }
    __syncthreads();

    // scores: f32x2 accumulation; 1/16 scale folded into q registers
    {
        int q = tid >> 3, g = tid & 7;
        float qr[32];
        #pragma unroll
        for (int d = 0; d < 32; d++) qr[d] = Qs[q][d] * 0.0625f;
        #pragma unroll
        for (int kk = 0; kk < 7; kk++) {
            int j0 = g * 4 + kk * 32;
            if (j0 >= NTOK) break;
            unsigned long long a01 = 0ull, a23 = 0ull;
            #pragma unroll
            for (int d = 0; d < 32; d++) {
                unsigned long long aq = pk2(qr[d], qr[d]);
                ulonglong2 kv = *(ulonglong2*)&Ks[d][j0];
                ffma2(a01, aq, kv.x);
                ffma2(a23, aq, kv.y);
            }
            float2 r01 = up2(a01), r23 = up2(a23);
            *(float4*)&Ss[q][j0] = make_float4(r01.x, r01.y, r23.x, r23.y);
        }
    }
    __syncthreads();

    // softmax
    {
        int w = tid >> 5, lane = tid & 31;
        for (int r = 0; r < 4; r++) {
            int q = w * 4 + r;
            float m = -1e30f;
            for (int j = lane; j < NTOK; j += 32) m = fmaxf(m, Ss[q][j]);
            #pragma unroll
            for (int off = 16; off; off >>= 1)
                m = fmaxf(m, __shfl_xor_sync(0xffffffffu, m, off));
            float sum = 0.f;
            for (int j = lane; j < NTOK; j += 32) {
                float e = __expf(Ss[q][j] - m);
                Ss[q][j] = e;
                sum += e;
            }
            #pragma unroll
            for (int off = 16; off; off >>= 1)
                sum += __shfl_xor_sync(0xffffffffu, sum, off);
            if (lane == 0) inv[q] = 1.0f / sum;
        }
    }
    __syncthreads();

    // PV: f32x2 accumulation, p-pairs loaded as float2
    {
        int q = tid >> 3, d0 = (tid & 7) * 4;
        unsigned long long acc01 = 0ull, acc23 = 0ull;
        for (int j = 0; j < NTOK; j += 2) {
            float2 pp = *(float2*)&Ss[q][j];
            unsigned long long p0 = pk2(pp.x, pp.x);
            unsigned long long p1 = pk2(pp.y, pp.y);
            ulonglong2 v0 = *(ulonglong2*)&Vs[j][d0];
            ulonglong2 v1 = *(ulonglong2*)&Vs[j + 1][d0];
            ffma2(acc01, p0, v0.x); ffma2(acc23, p0, v0.y);
            ffma2(acc01, p1, v1.x); ffma2(acc23, p1, v1.y);
        }
        float iv = inv[q];
        float2 r01 = up2(acc01), r23 = up2(acc23);
        float4 o = make_float4(r01.x * iv, r01.y * iv, r23.x * iv, r23.y * iv);
        int qg = qt * 32 + q;
        if (qg < NTOK)
            *(float4*)&g_attn[s][qg * EMBD + h * DHD + d0] = o;
    }
}

// ---------------- fused persistent kernel ----------------
struct Params {
    const float *vis, *ir;
    const float *ln1w[2], *ln1b[2], *ln2w[2], *ln2b[2];
    const float *Wqkv[2], *bqkv[2], *Wp[2], *bp[2];
    const float *W1[2], *b1[2], *W2[2], *b2[2];
    float* out;
};

__global__ void __launch_bounds__(NTHR, 2) fused(Params p)
{
    extern __shared__ float sm[];
    int b = blockIdx.x;
    int tid = threadIdx.x;
    int tx = mt_tx(tid), ty = mt_ty(tid);
    unsigned long long acc[4][2];

    // ---- S0: QKV GEMM K=256 (96 items, 64x64) w/ fused bias + deinterleave,
    //          LN1 on the remaining 200 blocks ----
    if (b < 96) {
        int t = b;
        int nt = t % 12; t /= 12;
        int mt = t % 4; t /= 4;
        int s = t;
        int row0 = mt * 64, col0 = nt * 64;
        gemm_main(s ? p.ir : p.vis, EMBD, NTOK, p.Wqkv[s], 768,
                  row0, col0, 0, 256, sm, acc);
        const float* bq = p.bqkv[s];
        #pragma unroll
        for (int i = 0; i < 4; i++) {
            int n = row0 + ty * 4 + i;
            if (n < NTOK) {
                float v[4];
                unpack_row(acc, i, v);
                #pragma unroll
                for (int j = 0; j < 4; j++) {
                    int c = col0 + tx * 4 + j;
                    float val = v[j] + bq[c];
                    int hd = c / 3, t3 = c - hd * 3;
                    int h = hd >> 5, d = hd & 31;
                    if (t3 == 0)      g_q[s][h][n * DHD + d] = val;
                    else if (t3 == 1) g_k[s][h][d * 200 + n] = val;
                    else              g_v[s][h][n * DHD + d] = val;
                }
            }
        }
    } else {
        for (int r = b - 96; r < 2 * NTOK; r += NB - 96) {
            int s = r >= NTOK;
            int n = s ? r - NTOK : r;
            float v = (s ? p.ir : p.vis)[n * EMBD + tid];
            g_nrm1[s][n * EMBD + tid] =
                ln_norm(v, p.ln1w[s][tid], p.ln1b[s][tid], sm);
        }
    }
    gsync();

    // ---- S1: cross attention (112 items) ----
    if (b < 112) {
        int t = b;
        int qt = t % 7; t /= 7;
        int h = t % 8;
        int s = t / 8;
        attn_tile(qt, h, s, sm);
    }
    gsync();

    // ---- S2: proj split-K=4 partial GEMMs (128 items, 64x64, K=64) ----
    if (b < 128) {
        int t = b;
        int nt = t & 3; t >>= 2;
        int mt = t & 3; t >>= 2;
        int s = t & 1, ks = t >> 1;
        int row0 = mt * 64, col0 = nt * 64;
        gemm_main(g_attn[s], EMBD, NTOK, p.Wp[s], EMBD,
                  row0, col0, ks * 64, 64, sm, acc);
        float* Cp = g_part[ks * 2 + s];
        #pragma unroll
        for (int i = 0; i < 4; i++) {
            int r = row0 + ty * 4 + i;
            if (r < NTOK) {
                float v[4];
                unpack_row(acc, i, v);
                *(float4*)&Cp[r * EMBD + col0 + tx * 4] = *(float4*)&v[0];
            }
        }
    }
    gsync();

    // ---- S3: proj reduce + bias + residual + LN2 ----
    for (int r = b; r < 2 * NTOK; r += NB) {
        int s = r >= NTOK;
        int n = s ? r - NTOK : r;
        int idx = n * EMBD + tid;
        float v = g_part[s][idx] + g_part[2 + s][idx] +
                  g_part[4 + s][idx] + g_part[6 + s][idx] +
                  p.bp[s][tid] + g_nrm1[s][idx];
        g_l[s][idx] = ln_norm(v, p.ln2w[s][tid], p.ln2b[s][tid], sm);
    }
    gsync();

    // ---- S4: FF1 GEMM K=256 (128 items, 64x64) w/ fused bias + exact GELU ----
    if (b < 128) {
        int t = b;
        int nt = t & 15; t >>= 4;
        int mt = t & 3; t >>= 2;
        int s = t;
        int row0 = mt * 64, col0 = nt * 64;
        gemm_main(g_l[s], EMBD, NTOK, p.W1[s], HIDD,
                  row0, col0, 0, 256, sm, acc);
        const float* b1 = p.b1[s];
        #pragma unroll
        for (int i = 0; i < 4; i++) {
            int r = row0 + ty * 4 + i;
            if (r < NTOK) {
                float v[4];
                unpack_row(acc, i, v);
                #pragma unroll
                for (int j = 0; j < 4; j++) {
                    float x = v[j] + b1[col0 + tx * 4 + j];
                    v[j] = 0.5f * x * (1.0f + erff(x * 0.70710678118654752f));
                }
                *(float4*)&g_hid[s][r * HIDD + col0 + tx * 4] = *(float4*)&v[0];
            }
        }
    }
    gsync();

    // ---- S5: FF2 split-K=8 partial GEMMs (256 items, 64x64, K=128) ----
    if (b < 256) {
        int t = b;
        int nt = t & 3; t >>= 2;
        int mt = t & 3; t >>= 2;
        int s = t & 1, ks = t >> 1;      // ks 0..7
        int row0 = mt * 64, col0 = nt * 64;
        gemm_main(g_hid[s], HIDD, NTOK, p.W2[s], EMBD,
                  row0, col0, ks * 128, 128, sm, acc);
        float* Cp = g_part[ks * 2 + s];
        #pragma unroll
        for (int i = 0; i < 4; i++) {
            int r = row0 + ty * 4 + i;
            if (r < NTOK) {
                float v[4];
                unpack_row(acc, i, v);
                *(float4*)&Cp[r * EMBD + col0 + tx * 4] = *(float4*)&v[0];
            }
        }
    }
    gsync();

    // ---- S6: FF2 reduce + bias + residual + pixel-shuffle to d_out ----
    for (int r = b; r < 2 * NTOK; r += NB) {
        int s = r >= NTOK;
        int n = s ? r - NTOK : r;
        int idx = n * EMBD + tid;
        float v = 0.f;
        #pragma unroll
        for (int ks = 0; ks < 8; ks++) v += g_part[ks * 2 + s][idx];
        v += p.b2[s][tid] + g_l[s][idx];
        int i = n / 14, j = n % 14;
        int pp = tid >> 4, q = tid & 15;
        int ch = s ? 0 : 1;
        p.out[ch * 50176 + pp * 3136 + q * 196 + i * 14 + j] = v;
    }
}

// ---------------- launch ----------------
extern "C" void kernel_launch(void* const* d_in, const int* in_sizes, int n_in,
                              void* d_out, int out_size)
{
    Params pr;
    pr.vis = (const float*)d_in[0];
    pr.ir  = (const float*)d_in[1];
    pr.ln1w[0] = (const float*)d_in[2];  pr.ln1b[0] = (const float*)d_in[3];
    pr.ln1w[1] = (const float*)d_in[4];  pr.ln1b[1] = (const float*)d_in[5];
    pr.ln2w[0] = (const float*)d_in[6];  pr.ln2b[0] = (const float*)d_in[7];
    pr.ln2w[1] = (const float*)d_in[8];  pr.ln2b[1] = (const float*)d_in[9];
    pr.Wqkv[0] = (const float*)d_in[10]; pr.bqkv[0] = (const float*)d_in[11];
    pr.Wqkv[1] = (const float*)d_in[12]; pr.bqkv[1] = (const float*)d_in[13];
    pr.Wp[0]   = (const float*)d_in[14]; pr.bp[0]   = (const float*)d_in[15];
    pr.Wp[1]   = (const float*)d_in[16]; pr.bp[1]   = (const float*)d_in[17];
    pr.W1[0]   = (const float*)d_in[18]; pr.b1[0]   = (const float*)d_in[19];
    pr.W2[0]   = (const float*)d_in[20]; pr.b2[0]   = (const float*)d_in[21];
    pr.W1[1]   = (const float*)d_in[22]; pr.b1[1]   = (const float*)d_in[23];
    pr.W2[1]   = (const float*)d_in[24]; pr.b2[1]   = (const float*)d_in[25];
    pr.out = (float*)d_out;

    cudaFuncSetAttribute(fused, cudaFuncAttributeMaxDynamicSharedMemorySize,
                         SMEM_BYTES);
    fused<<<NB, NTHR, SMEM_BYTES>>>(pr);
}